// round 1
// baseline (speedup 1.0000x reference)
#include <cuda_runtime.h>
#include <cstdint>
#include <cmath>

// Problem constants (fixed by the dataset)
#define EE 800000
#define NN 50000
#define DH 128
#define BN_EPS 1e-5f

// ---------------------------------------------------------------------------
// Scratch (device globals; no allocation at runtime)
// ---------------------------------------------------------------------------
__device__ float g_h1 [(size_t)EE * DH];   // edge layer-1 raw matmul out
__device__ float g_h2 [(size_t)EE * DH];   // edge layer-2 raw matmul out
__device__ float g_o1 [(size_t)NN * DH];   // node layer-1 raw matmul out
__device__ float g_o2 [(size_t)NN * DH];   // node layer-2 raw matmul out
__device__ float g_agg[(size_t)NN * DH];   // scatter-sum accumulator
__device__ int   g_cnt[NN];                // per-node edge counts
__device__ float g_sum  [512];             // 4 layers x 128 col sums
__device__ float g_sumsq[512];             // 4 layers x 128 col sumsq
__device__ float g_scale[512];             // folded BN scale per layer
__device__ float g_shift[512];             // folded BN shift per layer

// ---------------------------------------------------------------------------
// Helpers
// ---------------------------------------------------------------------------
__device__ __forceinline__ uint32_t f2tf32(float x) {
    uint32_t r;
    asm("cvt.rna.tf32.f32 %0, %1;" : "=r"(r) : "f"(x));
    return r;
}
__device__ __forceinline__ float tf32f(float x) {
    return __uint_as_float(f2tf32(x));
}

__device__ __forceinline__ void mma_tf32(float* c, const uint32_t* a, const uint32_t* b) {
    asm volatile(
        "mma.sync.aligned.m16n8k8.row.col.f32.tf32.tf32.f32 "
        "{%0,%1,%2,%3}, {%4,%5,%6,%7}, {%8,%9}, {%0,%1,%2,%3};"
        : "+f"(c[0]), "+f"(c[1]), "+f"(c[2]), "+f"(c[3])
        : "r"(a[0]), "r"(a[1]), "r"(a[2]), "r"(a[3]), "r"(b[0]), "r"(b[1]));
}

// ---------------------------------------------------------------------------
// Tiled tf32 GEMM: out[M,128] = A[M,K] @ W[K,128]
// MODE 0: A = concat(message, x[row])              (K=256, edge layer 1)
// MODE 1: A = relu(prev*scale + shift)             (K=128, layer 2 of each MLP)
// MODE 2: A = concat(x, agg_sum * inv_cnt)         (K=256, node layer 1)
// Block tile 128x128, BK=32, 256 threads, 8 warps (4 in M x 2 in N),
// warp tile 32x64, per-warp mma grid 2x8 of m16n8k8.
// ---------------------------------------------------------------------------
template<int MODE>
__launch_bounds__(256, 2)
__global__ void gemm_tf32(
    const float* __restrict__ A0,    // mode0: message; mode1: prev; mode2: x
    const float* __restrict__ A1,    // mode0: x; mode2: agg sums
    const int*   __restrict__ ridx,  // mode0: edge row indices
    const int*   __restrict__ cnt,   // mode2: per-node counts
    const float* __restrict__ scl,   // mode1
    const float* __restrict__ sft,   // mode1
    const float* __restrict__ W,     // [K,128] row-major
    float* __restrict__ Hout,        // [M,128]
    int M)
{
    constexpr int K = (MODE == 1) ? 128 : 256;

    __shared__ float sA[128 * 36];   // [row][k], stride 36 (conflict-free frag loads)
    __shared__ float sB[32 * 136];   // [k][n],  stride 136 (conflict-free frag loads)
    __shared__ int   sRow[128];
    __shared__ float sInv[128];

    const int tid = threadIdx.x;
    const int bm  = blockIdx.x * 128;

    if (MODE == 0) {
        if (tid < 128) sRow[tid] = ridx[bm + tid];
    }
    if (MODE == 2) {
        if (tid < 128) {
            int r = bm + tid;
            int c = (r < M) ? cnt[r] : 1;
            sInv[tid] = 1.0f / (float)(c > 1 ? c : 1);
        }
    }
    if (MODE == 0 || MODE == 2) __syncthreads();

    float acc[2][8][4];
#pragma unroll
    for (int mi = 0; mi < 2; mi++)
#pragma unroll
        for (int ni = 0; ni < 8; ni++)
#pragma unroll
            for (int v = 0; v < 4; v++) acc[mi][ni][v] = 0.0f;

    const int lane = tid & 31;
    const int warp = tid >> 5;
    const int g    = lane >> 2;     // group id 0..7
    const int t4   = lane & 3;      // thread-in-group 0..3
    const int wm   = warp & 3;      // warp M coord (0..3)
    const int wn   = warp >> 2;     // warp N coord (0..1)
    const int wr   = wm * 32;
    const int wc   = wn * 64;

    for (int k0 = 0; k0 < K; k0 += 32) {
        // ---- stage A tile: 128 rows x 32 cols (1024 float4, 4 per thread) ----
#pragma unroll
        for (int j = 0; j < 4; j++) {
            int f4  = tid + j * 256;
            int row = f4 >> 3;
            int c4  = f4 & 7;
            int rg  = bm + row;
            float4 v = make_float4(0.f, 0.f, 0.f, 0.f);
            if (MODE == 0) {
                const float* base = (k0 < 128)
                    ? (A0 + (size_t)rg * 128 + k0)
                    : (A1 + (size_t)sRow[row] * 128 + (k0 - 128));
                v = *(const float4*)(base + c4 * 4);
            } else if (MODE == 1) {
                if (rg < M) {
                    v = *(const float4*)(A0 + (size_t)rg * 128 + k0 + c4 * 4);
                    float4 s = *(const float4*)(scl + k0 + c4 * 4);
                    float4 h = *(const float4*)(sft + k0 + c4 * 4);
                    v.x = fmaxf(fmaf(v.x, s.x, h.x), 0.f);
                    v.y = fmaxf(fmaf(v.y, s.y, h.y), 0.f);
                    v.z = fmaxf(fmaf(v.z, s.z, h.z), 0.f);
                    v.w = fmaxf(fmaf(v.w, s.w, h.w), 0.f);
                }
            } else { // MODE 2
                if (rg < M) {
                    if (k0 < 128) {
                        v = *(const float4*)(A0 + (size_t)rg * 128 + k0 + c4 * 4);
                    } else {
                        v = *(const float4*)(A1 + (size_t)rg * 128 + (k0 - 128) + c4 * 4);
                        float iv = sInv[row];
                        v.x *= iv; v.y *= iv; v.z *= iv; v.w *= iv;
                    }
                }
            }
            float4 t = make_float4(tf32f(v.x), tf32f(v.y), tf32f(v.z), tf32f(v.w));
            *(float4*)(sA + row * 36 + c4 * 4) = t;
        }
        // ---- stage B tile: 32 rows x 128 cols (1024 float4, 4 per thread) ----
#pragma unroll
        for (int j = 0; j < 4; j++) {
            int f4 = tid + j * 256;
            int kr = f4 >> 5;
            int c4 = f4 & 31;
            float4 v = *(const float4*)(W + (size_t)(k0 + kr) * 128 + c4 * 4);
            float4 t = make_float4(tf32f(v.x), tf32f(v.y), tf32f(v.z), tf32f(v.w));
            *(float4*)(sB + kr * 136 + c4 * 4) = t;
        }
        __syncthreads();

#pragma unroll
        for (int kk = 0; kk < 32; kk += 8) {
            uint32_t a[2][4];
            uint32_t b[8][2];
#pragma unroll
            for (int mi = 0; mi < 2; mi++) {
                int rb = wr + mi * 16;
                a[mi][0] = __float_as_uint(sA[(rb + g    ) * 36 + kk + t4    ]);
                a[mi][1] = __float_as_uint(sA[(rb + g + 8) * 36 + kk + t4    ]);
                a[mi][2] = __float_as_uint(sA[(rb + g    ) * 36 + kk + t4 + 4]);
                a[mi][3] = __float_as_uint(sA[(rb + g + 8) * 36 + kk + t4 + 4]);
            }
#pragma unroll
            for (int ni = 0; ni < 8; ni++) {
                int n = wc + ni * 8 + g;
                b[ni][0] = __float_as_uint(sB[(kk + t4    ) * 136 + n]);
                b[ni][1] = __float_as_uint(sB[(kk + t4 + 4) * 136 + n]);
            }
#pragma unroll
            for (int mi = 0; mi < 2; mi++)
#pragma unroll
                for (int ni = 0; ni < 8; ni++)
                    mma_tf32(acc[mi][ni], a[mi], b[ni]);
        }
        __syncthreads();
    }

    // ---- epilogue: write raw matmul outputs ----
#pragma unroll
    for (int mi = 0; mi < 2; mi++) {
        int r0 = bm + wr + mi * 16 + g;
        int r1 = r0 + 8;
#pragma unroll
        for (int ni = 0; ni < 8; ni++) {
            int cc = wc + ni * 8 + 2 * t4;
            if (r0 < M) *(float2*)(Hout + (size_t)r0 * 128 + cc) =
                make_float2(acc[mi][ni][0], acc[mi][ni][1]);
            if (r1 < M) *(float2*)(Hout + (size_t)r1 * 128 + cc) =
                make_float2(acc[mi][ni][2], acc[mi][ni][3]);
        }
    }
}

// ---------------------------------------------------------------------------
// Column statistics: per-feature sum and sum-of-squares over M rows
// ---------------------------------------------------------------------------
__global__ void stats_kernel(const float* __restrict__ H, int M,
                             float* __restrict__ sum, float* __restrict__ sumsq)
{
    __shared__ float ss[128], sq[128];
    int t = threadIdx.x;                 // 256 threads
    if (t < 128) { ss[t] = 0.f; sq[t] = 0.f; }
    __syncthreads();

    int c4 = (t & 31) * 4;               // 4 columns per thread
    int rl = t >> 5;                     // 8 row lanes
    float s0 = 0, s1 = 0, s2 = 0, s3 = 0;
    float q0 = 0, q1 = 0, q2 = 0, q3 = 0;
    for (int r = blockIdx.x * 8 + rl; r < M; r += gridDim.x * 8) {
        float4 v = *(const float4*)(H + (size_t)r * 128 + c4);
        s0 += v.x; q0 += v.x * v.x;
        s1 += v.y; q1 += v.y * v.y;
        s2 += v.z; q2 += v.z * v.z;
        s3 += v.w; q3 += v.w * v.w;
    }
    atomicAdd(&ss[c4    ], s0); atomicAdd(&sq[c4    ], q0);
    atomicAdd(&ss[c4 + 1], s1); atomicAdd(&sq[c4 + 1], q1);
    atomicAdd(&ss[c4 + 2], s2); atomicAdd(&sq[c4 + 2], q2);
    atomicAdd(&ss[c4 + 3], s3); atomicAdd(&sq[c4 + 3], q3);
    __syncthreads();
    if (t < 128) {
        atomicAdd(&sum[t], ss[t]);
        atomicAdd(&sumsq[t], sq[t]);
    }
}

// Fold BN (training-mode, biased var) + gamma/beta into per-feature affine.
__global__ void finalize_kernel(const float* __restrict__ sum,
                                const float* __restrict__ sumsq,
                                const float* __restrict__ gamma,
                                const float* __restrict__ beta,
                                float invM,
                                float* __restrict__ scale,
                                float* __restrict__ shift)
{
    int t = threadIdx.x;                 // 128 threads
    float m  = sum[t] * invM;
    float v  = fmaxf(sumsq[t] * invM - m * m, 0.f);
    float sc = gamma[t] * rsqrtf(v + BN_EPS);
    scale[t] = sc;
    shift[t] = beta[t] - m * sc;
}

// Zero accumulators (agg, cnt, stats)
__global__ void zero_kernel(float* __restrict__ agg, int* __restrict__ cnt,
                            float* __restrict__ sum, float* __restrict__ sumsq)
{
    int idx = blockIdx.x * blockDim.x + threadIdx.x;
    if (idx < NN * DH) agg[idx] = 0.f;
    if (idx < NN)      cnt[idx] = 0;
    if (idx < 512) { sum[idx] = 0.f; sumsq[idx] = 0.f; }
}

// Scatter: agg[col[e]] += relu(bn2(h2[e])), cnt[col[e]] += 1
__global__ void scatter_kernel(const float* __restrict__ h2,
                               const int* __restrict__ col,
                               const float* __restrict__ scl,
                               const float* __restrict__ sft,
                               float* __restrict__ agg, int* __restrict__ cnt)
{
    int idx = blockIdx.x * 256 + threadIdx.x;   // EE*128 total
    int e = idx >> 7;
    if (e >= EE) return;
    int j = idx & 127;
    int c = __ldg(col + e);
    float v = fmaxf(fmaf(h2[idx], scl[j], sft[j]), 0.f);
    atomicAdd(agg + (size_t)c * 128 + j, v);
    if (j == 0) atomicAdd(cnt + c, 1);
}

// Final: o = relu(bn(o2raw)); attn = sigmoid(o @ wa + ba)
__global__ void output_kernel(const float* __restrict__ o2,
                              const float* __restrict__ scl,
                              const float* __restrict__ sft,
                              const float* __restrict__ wa,
                              const float* __restrict__ ba,
                              float* __restrict__ out)
{
    __shared__ float red[4];
    int n = blockIdx.x;
    int t = threadIdx.x;                 // 128 threads
    float v = o2[(size_t)n * 128 + t];
    v = fmaxf(fmaf(v, scl[t], sft[t]), 0.f);
    out[(size_t)n * 128 + t] = v;

    float p = v * wa[t];
#pragma unroll
    for (int off = 16; off > 0; off >>= 1)
        p += __shfl_xor_sync(0xFFFFFFFFu, p, off);
    if ((t & 31) == 0) red[t >> 5] = p;
    __syncthreads();
    if (t == 0) {
        float d = red[0] + red[1] + red[2] + red[3] + ba[0];
        out[(size_t)NN * 128 + n] = 1.0f / (1.0f + expf(-d));
    }
}

// ---------------------------------------------------------------------------
// Launch
// ---------------------------------------------------------------------------
extern "C" void kernel_launch(void* const* d_in, const int* in_sizes, int n_in,
                              void* d_out, int out_size)
{
    const float* x       = (const float*)d_in[0];
    const int*   ei      = (const int*)  d_in[1];   // [2,E]: row then col
    const float* message = (const float*)d_in[2];
    const float* w1a = (const float*)d_in[3];
    // d_in[4] b1a — cancels inside BN
    const float* g1a  = (const float*)d_in[5];
    const float* be1a = (const float*)d_in[6];
    const float* w1b  = (const float*)d_in[7];
    const float* g1b  = (const float*)d_in[9];
    const float* be1b = (const float*)d_in[10];
    const float* w2a  = (const float*)d_in[11];
    const float* g2a  = (const float*)d_in[13];
    const float* be2a = (const float*)d_in[14];
    const float* w2b  = (const float*)d_in[15];
    const float* g2b  = (const float*)d_in[17];
    const float* be2b = (const float*)d_in[18];
    const float* wa   = (const float*)d_in[19];
    const float* ba   = (const float*)d_in[20];
    float* out = (float*)d_out;

    float *h1, *h2, *o1, *o2, *agg, *sum, *sumsq, *scale, *shift;
    int* cnt;
    cudaGetSymbolAddress((void**)&h1,    g_h1);
    cudaGetSymbolAddress((void**)&h2,    g_h2);
    cudaGetSymbolAddress((void**)&o1,    g_o1);
    cudaGetSymbolAddress((void**)&o2,    g_o2);
    cudaGetSymbolAddress((void**)&agg,   g_agg);
    cudaGetSymbolAddress((void**)&cnt,   g_cnt);
    cudaGetSymbolAddress((void**)&sum,   g_sum);
    cudaGetSymbolAddress((void**)&sumsq, g_sumsq);
    cudaGetSymbolAddress((void**)&scale, g_scale);
    cudaGetSymbolAddress((void**)&shift, g_shift);

    const int* row = ei;        // edge_index[0]
    const int* col = ei + EE;   // edge_index[1]

    zero_kernel<<<(NN * DH + 1023) / 1024, 1024>>>(agg, cnt, sum, sumsq);

    // edge MLP layer 1: h1 = concat(message, x[row]) @ w1a
    gemm_tf32<0><<<EE / 128, 256>>>(message, x, row, nullptr, nullptr, nullptr,
                                    w1a, h1, EE);
    stats_kernel<<<1184, 256>>>(h1, EE, sum + 0, sumsq + 0);
    finalize_kernel<<<1, 128>>>(sum + 0, sumsq + 0, g1a, be1a, 1.0f / EE,
                                scale + 0, shift + 0);

    // edge MLP layer 2: h2 = relu(bn1(h1)) @ w1b
    gemm_tf32<1><<<EE / 128, 256>>>(h1, nullptr, nullptr, nullptr,
                                    scale + 0, shift + 0, w1b, h2, EE);
    stats_kernel<<<1184, 256>>>(h2, EE, sum + 128, sumsq + 128);
    finalize_kernel<<<1, 128>>>(sum + 128, sumsq + 128, g1b, be1b, 1.0f / EE,
                                scale + 128, shift + 128);

    // scatter-mean (sum + count here, divide fused into node GEMM A-load)
    scatter_kernel<<<(EE * 128) / 256, 256>>>(h2, col, scale + 128, shift + 128,
                                              agg, cnt);

    // node MLP layer 1: o1 = concat(x, agg/cnt) @ w2a
    gemm_tf32<2><<<(NN + 127) / 128, 256>>>(x, agg, nullptr, cnt, nullptr, nullptr,
                                            w2a, o1, NN);
    stats_kernel<<<1184, 256>>>(o1, NN, sum + 256, sumsq + 256);
    finalize_kernel<<<1, 128>>>(sum + 256, sumsq + 256, g2a, be2a, 1.0f / NN,
                                scale + 256, shift + 256);

    // node MLP layer 2: o2 = relu(bn3(o1)) @ w2b
    gemm_tf32<1><<<(NN + 127) / 128, 256>>>(o1, nullptr, nullptr, nullptr,
                                            scale + 256, shift + 256, w2b, o2, NN);
    stats_kernel<<<1184, 256>>>(o2, NN, sum + 384, sumsq + 384);
    finalize_kernel<<<1, 128>>>(sum + 384, sumsq + 384, g2b, be2b, 1.0f / NN,
                                scale + 384, shift + 384);

    // output: o (N*128 floats) then attn (N floats)
    output_kernel<<<NN, 128>>>(o2, scale + 384, shift + 384, wa, ba, out);
}

// round 2
// speedup vs baseline: 1.5781x; 1.5781x over previous
#include <cuda_runtime.h>
#include <cstdint>
#include <cmath>

// Problem constants (fixed by the dataset)
#define EE 800000
#define NN 50000
#define BN_EPS 1e-5f

// ---------------------------------------------------------------------------
// Scratch (device globals; no runtime allocation)
// ---------------------------------------------------------------------------
__device__ float g_h1 [(size_t)EE * 128];
__device__ float g_h2 [(size_t)EE * 128];
__device__ float g_o1 [(size_t)NN * 128];
__device__ float g_o2 [(size_t)NN * 128];
__device__ float g_agg[(size_t)NN * 128];
__device__ int   g_cnt[NN];
__device__ float g_sum  [512];      // 4 layers x 128 col sums
__device__ float g_sumsq[512];      // 4 layers x 128 col sumsq
__device__ float g_wc   [98304];    // tf32-pre-rounded weights (w1a,w1b,w2a,w2b)

// ---------------------------------------------------------------------------
// Helpers
// ---------------------------------------------------------------------------
__device__ __forceinline__ uint32_t f2tf32(float x) {
    uint32_t r;
    asm("cvt.rna.tf32.f32 %0, %1;" : "=r"(r) : "f"(x));
    return r;
}
__device__ __forceinline__ float tf32f(float x) { return __uint_as_float(f2tf32(x)); }

__device__ __forceinline__ void mma_tf32(float* c, const uint32_t* a, const uint32_t* b) {
    asm volatile(
        "mma.sync.aligned.m16n8k8.row.col.f32.tf32.tf32.f32 "
        "{%0,%1,%2,%3}, {%4,%5,%6,%7}, {%8,%9}, {%0,%1,%2,%3};"
        : "+f"(c[0]), "+f"(c[1]), "+f"(c[2]), "+f"(c[3])
        : "r"(a[0]), "r"(a[1]), "r"(a[2]), "r"(a[3]), "r"(b[0]), "r"(b[1]));
}

__device__ __forceinline__ void cp_async16(uint32_t dst, const void* src, int bytes) {
    asm volatile("cp.async.cg.shared.global [%0], [%1], 16, %2;"
                 :: "r"(dst), "l"(src), "r"(bytes));
}
__device__ __forceinline__ void cp_commit() {
    asm volatile("cp.async.commit_group;" ::: "memory");
}
template<int N>
__device__ __forceinline__ void cp_wait() {
    asm volatile("cp.async.wait_group %0;" :: "n"(N) : "memory");
}

__device__ __forceinline__ void red_add_v4(float* p, float4 v) {
    asm volatile("red.global.add.v4.f32 [%0], {%1,%2,%3,%4};"
                 :: "l"(p), "f"(v.x), "f"(v.y), "f"(v.z), "f"(v.w) : "memory");
}

// ---------------------------------------------------------------------------
// prep: zero accumulators + pre-round weights to tf32
// ---------------------------------------------------------------------------
__global__ void prep_kernel(float* __restrict__ agg, int* __restrict__ cnt,
                            float* __restrict__ sum, float* __restrict__ sumsq,
                            float* __restrict__ wc,
                            const float* __restrict__ w1a, const float* __restrict__ w1b,
                            const float* __restrict__ w2a, const float* __restrict__ w2b)
{
    int idx = blockIdx.x * blockDim.x + threadIdx.x;
    if (idx < NN * 128) agg[idx] = 0.f;
    if (idx < NN)       cnt[idx] = 0;
    if (idx < 512) { sum[idx] = 0.f; sumsq[idx] = 0.f; }
    if (idx < 98304) {
        float v;
        if      (idx < 32768) v = w1a[idx];
        else if (idx < 49152) v = w1b[idx - 32768];
        else if (idx < 81920) v = w2a[idx - 49152];
        else                  v = w2b[idx - 81920];
        wc[idx] = tf32f(v);
    }
}

// ---------------------------------------------------------------------------
// Pipelined tf32 GEMM: out[M,128] = A[M,K] @ W[K,128], fused BN-stat epilogue.
// MODE 0: A = concat(message, x[row])          (K=256, edge layer 1)
// MODE 1: A = relu(prev*scale + shift)         (K=128; scale/shift computed
//                                               in-kernel from prev layer stats)
// MODE 2: A = concat(x, agg_sum * inv_cnt)     (K=256, node layer 1)
// 128x128 block tile, BK=32, cp.async double-buffered, swizzled smem,
// cvt at fragment-load time (weights pre-rounded).
// ---------------------------------------------------------------------------
template<int MODE>
__launch_bounds__(256, 2)
__global__ void gemm_tf32(
    const float* __restrict__ A0,    // mode0: message; mode1: prev; mode2: x
    const float* __restrict__ A1,    // mode0: x; mode2: agg sums
    const int*   __restrict__ ridx,  // mode0: edge row indices
    const int*   __restrict__ cnt,   // mode2: per-node counts
    const float* __restrict__ psum,  // mode1: prev-layer col sums
    const float* __restrict__ psq,   // mode1: prev-layer col sumsq
    const float* __restrict__ gamma, // mode1
    const float* __restrict__ beta,  // mode1
    float        invPrevM,           // mode1
    const float* __restrict__ W,     // [K,128] tf32-pre-rounded
    float* __restrict__ Hout,        // [M,128]
    int M,
    float* __restrict__ osum,        // this layer's col-sum slot
    float* __restrict__ osq)         // this layer's col-sumsq slot
{
    constexpr int K    = (MODE == 1) ? 128 : 256;
    constexpr int NIT  = K / 32;

    extern __shared__ float dynsm[];           // [2][A:128*32 | B:32*128]
    __shared__ int   sRow[128];
    __shared__ float sInv[128];
    __shared__ float sScl[128], sSft[128];
    __shared__ float sSum[128], sSq[128];

    const int tid = threadIdx.x;
    const int bm  = blockIdx.x * 128;

    if (tid < 128) { sSum[tid] = 0.f; sSq[tid] = 0.f; }
    if (MODE == 0 && tid < 128) sRow[tid] = ridx[bm + tid];
    if (MODE == 2 && tid < 128) {
        int r = bm + tid;
        int c = (r < M) ? cnt[r] : 1;
        sInv[tid] = 1.0f / (float)(c > 1 ? c : 1);
    }
    if (MODE == 1 && tid < 128) {
        float m  = psum[tid] * invPrevM;
        float v  = fmaxf(psq[tid] * invPrevM - m * m, 0.f);
        float sc = gamma[tid] * rsqrtf(v + BN_EPS);
        sScl[tid] = sc;
        sSft[tid] = beta[tid] - m * sc;
    }
    __syncthreads();

    const uint32_t smemBase = (uint32_t)__cvta_generic_to_shared(dynsm);

    // stage one 128x32 A-tile + 32x128 B-tile into buffer s (cp.async)
    auto stage = [&](int k0, int s) {
        uint32_t aB = smemBase + s * 32768u;
        uint32_t bB = smemBase + s * 32768u + 16384u;
#pragma unroll
        for (int j = 0; j < 4; j++) {
            int f4  = tid + j * 256;
            int row = f4 >> 3;
            int c4  = f4 & 7;
            uint32_t dst = aB + (uint32_t)(row * 8 + (c4 ^ (row & 7))) * 16u;
            const float* src;
            int bytes = 16;
            if (MODE == 0) {
                src = (k0 < 128)
                    ? (A0 + (size_t)(bm + row) * 128 + k0 + c4 * 4)
                    : (A1 + (size_t)sRow[row] * 128 + (k0 - 128) + c4 * 4);
            } else if (MODE == 1) {
                int rg = bm + row;
                src = A0 + (size_t)rg * 128 + k0 + c4 * 4;
                bytes = (rg < M) ? 16 : 0;
            } else {
                int rg = bm + row;
                src = (k0 < 128)
                    ? (A0 + (size_t)rg * 128 + k0 + c4 * 4)
                    : (A1 + (size_t)rg * 128 + (k0 - 128) + c4 * 4);
                bytes = (rg < M) ? 16 : 0;
            }
            cp_async16(dst, src, bytes);
        }
#pragma unroll
        for (int j = 0; j < 4; j++) {
            int f4 = tid + j * 256;
            int kf = f4 >> 5;
            int n4 = f4 & 31;
            uint32_t dst = bB + (uint32_t)(kf * 32 + (n4 ^ (2 * (kf & 3)))) * 16u;
            cp_async16(dst, W + (size_t)(k0 + kf) * 128 + n4 * 4, 16);
        }
        cp_commit();
    };

    float acc[2][8][4];
#pragma unroll
    for (int mi = 0; mi < 2; mi++)
#pragma unroll
        for (int ni = 0; ni < 8; ni++)
#pragma unroll
            for (int v = 0; v < 4; v++) acc[mi][ni][v] = 0.0f;

    const int lane = tid & 31;
    const int warp = tid >> 5;
    const int g    = lane >> 2;
    const int t4   = lane & 3;
    const int wm   = warp & 3;
    const int wn   = warp >> 2;
    const int wr   = wm * 32;
    const int wc   = wn * 64;

    // per-thread inv-count for MODE 2 second K-half (rows fixed per thread)
    float inva[2][2];
    if (MODE == 2) {
#pragma unroll
        for (int mi = 0; mi < 2; mi++) {
            inva[mi][0] = sInv[wr + mi * 16 + g];
            inva[mi][1] = sInv[wr + mi * 16 + g + 8];
        }
    }

    stage(0, 0);

#pragma unroll 1
    for (int it = 0; it < NIT; it++) {
        const int s  = it & 1;
        const int k0 = it * 32;
        if (it + 1 < NIT) stage(k0 + 32, s ^ 1);
        if (it + 1 < NIT) cp_wait<1>(); else cp_wait<0>();
        __syncthreads();

        const float* As = dynsm + s * 8192;
        const float* Bs = dynsm + s * 8192 + 4096;
        const bool scale2 = (MODE == 2) && (k0 >= 128);

#pragma unroll
        for (int kk = 0; kk < 32; kk += 8) {
            uint32_t a[2][4];
            uint32_t b[8][2];
            const int klo = (kk >> 2);
            const int g0  = (klo ^ g) * 4 + t4;
            const int g1  = ((klo + 1) ^ g) * 4 + t4;
#pragma unroll
            for (int mi = 0; mi < 2; mi++) {
                int r0 = wr + mi * 16 + g;
                int r1 = r0 + 8;
                float v0 = As[r0 * 32 + g0];   // (r0, kk+t4)
                float v1 = As[r1 * 32 + g0];   // (r1, kk+t4)
                float v2 = As[r0 * 32 + g1];   // (r0, kk+t4+4)
                float v3 = As[r1 * 32 + g1];   // (r1, kk+t4+4)
                if (MODE == 1) {
                    int klo_g = k0 + kk + t4, khi_g = klo_g + 4;
                    float sl = sScl[klo_g], fl = sSft[klo_g];
                    float sh = sScl[khi_g], fh = sSft[khi_g];
                    v0 = fmaxf(fmaf(v0, sl, fl), 0.f);
                    v1 = fmaxf(fmaf(v1, sl, fl), 0.f);
                    v2 = fmaxf(fmaf(v2, sh, fh), 0.f);
                    v3 = fmaxf(fmaf(v3, sh, fh), 0.f);
                }
                if (scale2) {
                    v0 *= inva[mi][0]; v1 *= inva[mi][1];
                    v2 *= inva[mi][0]; v3 *= inva[mi][1];
                }
                a[mi][0] = f2tf32(v0);
                a[mi][1] = f2tf32(v1);
                a[mi][2] = f2tf32(v2);
                a[mi][3] = f2tf32(v3);
            }
#pragma unroll
            for (int ni = 0; ni < 8; ni++) {
                int m2 = (wc + ni * 8) >> 2;           // even
                int cp = ((m2 + (g >> 2)) ^ (2 * t4)) * 4 + (g & 3);
                b[ni][0] = __float_as_uint(Bs[(kk + t4    ) * 128 + cp]);
                b[ni][1] = __float_as_uint(Bs[(kk + t4 + 4) * 128 + cp]);
            }
#pragma unroll
            for (int mi = 0; mi < 2; mi++)
#pragma unroll
                for (int ni = 0; ni < 8; ni++)
                    mma_tf32(acc[mi][ni], a[mi], b[ni]);
        }
        __syncthreads();
    }

    // ---- fused BN-stat epilogue (padded rows contribute exact zeros) ----
#pragma unroll
    for (int ni = 0; ni < 8; ni++) {
        float s0 = 0, q0 = 0, s1 = 0, q1 = 0;
#pragma unroll
        for (int mi = 0; mi < 2; mi++) {
            float a0 = acc[mi][ni][0], a2 = acc[mi][ni][2];
            float a1 = acc[mi][ni][1], a3 = acc[mi][ni][3];
            s0 += a0 + a2; q0 += a0 * a0 + a2 * a2;
            s1 += a1 + a3; q1 += a1 * a1 + a3 * a3;
        }
#pragma unroll
        for (int off = 4; off < 32; off <<= 1) {
            s0 += __shfl_xor_sync(0xFFFFFFFFu, s0, off);
            q0 += __shfl_xor_sync(0xFFFFFFFFu, q0, off);
            s1 += __shfl_xor_sync(0xFFFFFFFFu, s1, off);
            q1 += __shfl_xor_sync(0xFFFFFFFFu, q1, off);
        }
        if (lane < 4) {  // g == 0
            int c0 = wc + ni * 8 + 2 * t4;
            atomicAdd(&sSum[c0],     s0); atomicAdd(&sSq[c0],     q0);
            atomicAdd(&sSum[c0 + 1], s1); atomicAdd(&sSq[c0 + 1], q1);
        }
    }
    __syncthreads();
    if (tid < 128) {
        atomicAdd(osum + tid, sSum[tid]);
        atomicAdd(osq  + tid, sSq[tid]);
    }

    // ---- write raw matmul outputs ----
#pragma unroll
    for (int mi = 0; mi < 2; mi++) {
        int r0 = bm + wr + mi * 16 + g;
        int r1 = r0 + 8;
#pragma unroll
        for (int ni = 0; ni < 8; ni++) {
            int cc = wc + ni * 8 + 2 * t4;
            if (r0 < M) *(float2*)(Hout + (size_t)r0 * 128 + cc) =
                make_float2(acc[mi][ni][0], acc[mi][ni][1]);
            if (r1 < M) *(float2*)(Hout + (size_t)r1 * 128 + cc) =
                make_float2(acc[mi][ni][2], acc[mi][ni][3]);
        }
    }
}

// ---------------------------------------------------------------------------
// Scatter: agg[col[e]] += relu(bn2(h2[e])), cnt[col[e]] += 1
// One warp per edge, vector red.global.add.v4.f32.
// ---------------------------------------------------------------------------
__global__ void scatter_kernel(const float* __restrict__ h2,
                               const int* __restrict__ col,
                               const float* __restrict__ psum,
                               const float* __restrict__ psq,
                               const float* __restrict__ gamma,
                               const float* __restrict__ beta,
                               float* __restrict__ agg, int* __restrict__ cnt)
{
    __shared__ float sScl[128], sSft[128];
    int t = threadIdx.x;                 // 256
    if (t < 128) {
        float m  = psum[t] * (1.0f / EE);
        float v  = fmaxf(psq[t] * (1.0f / EE) - m * m, 0.f);
        float sc = gamma[t] * rsqrtf(v + BN_EPS);
        sScl[t] = sc;
        sSft[t] = beta[t] - m * sc;
    }
    __syncthreads();

    int e    = blockIdx.x * 8 + (t >> 5);
    int lane = t & 31;
    int c    = __ldg(col + e);
    float4 v  = *(const float4*)(h2 + (size_t)e * 128 + lane * 4);
    float4 sc = *(const float4*)(sScl + lane * 4);
    float4 sf = *(const float4*)(sSft + lane * 4);
    v.x = fmaxf(fmaf(v.x, sc.x, sf.x), 0.f);
    v.y = fmaxf(fmaf(v.y, sc.y, sf.y), 0.f);
    v.z = fmaxf(fmaf(v.z, sc.z, sf.z), 0.f);
    v.w = fmaxf(fmaf(v.w, sc.w, sf.w), 0.f);
    red_add_v4(agg + (size_t)c * 128 + lane * 4, v);
    if (lane == 0) atomicAdd(cnt + c, 1);
}

// ---------------------------------------------------------------------------
// Final: o = relu(bn(o2raw)); attn = sigmoid(o @ wa + ba)
// ---------------------------------------------------------------------------
__global__ void output_kernel(const float* __restrict__ o2,
                              const float* __restrict__ psum,
                              const float* __restrict__ psq,
                              const float* __restrict__ gamma,
                              const float* __restrict__ beta,
                              const float* __restrict__ wa,
                              const float* __restrict__ ba,
                              float* __restrict__ out)
{
    __shared__ float red[4];
    int n = blockIdx.x;
    int t = threadIdx.x;                 // 128
    float m  = psum[t] * (1.0f / NN);
    float vv = fmaxf(psq[t] * (1.0f / NN) - m * m, 0.f);
    float sc = gamma[t] * rsqrtf(vv + BN_EPS);
    float sf = beta[t] - m * sc;

    float v = o2[(size_t)n * 128 + t];
    v = fmaxf(fmaf(v, sc, sf), 0.f);
    out[(size_t)n * 128 + t] = v;

    float p = v * wa[t];
#pragma unroll
    for (int off = 16; off > 0; off >>= 1)
        p += __shfl_xor_sync(0xFFFFFFFFu, p, off);
    if ((t & 31) == 0) red[t >> 5] = p;
    __syncthreads();
    if (t == 0) {
        float d = red[0] + red[1] + red[2] + red[3] + ba[0];
        out[(size_t)NN * 128 + n] = 1.0f / (1.0f + expf(-d));
    }
}

// ---------------------------------------------------------------------------
// Launch
// ---------------------------------------------------------------------------
extern "C" void kernel_launch(void* const* d_in, const int* in_sizes, int n_in,
                              void* d_out, int out_size)
{
    const float* x       = (const float*)d_in[0];
    const int*   ei      = (const int*)  d_in[1];   // [2,E]: row then col
    const float* message = (const float*)d_in[2];
    const float* w1a  = (const float*)d_in[3];
    const float* g1a  = (const float*)d_in[5];
    const float* be1a = (const float*)d_in[6];
    const float* w1b  = (const float*)d_in[7];
    const float* g1b  = (const float*)d_in[9];
    const float* be1b = (const float*)d_in[10];
    const float* w2a  = (const float*)d_in[11];
    const float* g2a  = (const float*)d_in[13];
    const float* be2a = (const float*)d_in[14];
    const float* w2b  = (const float*)d_in[15];
    const float* g2b  = (const float*)d_in[17];
    const float* be2b = (const float*)d_in[18];
    const float* wa   = (const float*)d_in[19];
    const float* ba   = (const float*)d_in[20];
    float* out = (float*)d_out;

    float *h1, *h2, *o1, *o2, *agg, *sum, *sumsq, *wc;
    int* cnt;
    cudaGetSymbolAddress((void**)&h1,    g_h1);
    cudaGetSymbolAddress((void**)&h2,    g_h2);
    cudaGetSymbolAddress((void**)&o1,    g_o1);
    cudaGetSymbolAddress((void**)&o2,    g_o2);
    cudaGetSymbolAddress((void**)&agg,   g_agg);
    cudaGetSymbolAddress((void**)&cnt,   g_cnt);
    cudaGetSymbolAddress((void**)&sum,   g_sum);
    cudaGetSymbolAddress((void**)&sumsq, g_sumsq);
    cudaGetSymbolAddress((void**)&wc,    g_wc);

    const int* row = ei;
    const int* col = ei + EE;

    static bool attr_done = false;
    if (!attr_done) {
        cudaFuncSetAttribute(gemm_tf32<0>, cudaFuncAttributeMaxDynamicSharedMemorySize, 65536);
        cudaFuncSetAttribute(gemm_tf32<1>, cudaFuncAttributeMaxDynamicSharedMemorySize, 65536);
        cudaFuncSetAttribute(gemm_tf32<2>, cudaFuncAttributeMaxDynamicSharedMemorySize, 65536);
        attr_done = true;
    }

    prep_kernel<<<(NN * 128 + 1023) / 1024, 1024>>>(agg, cnt, sum, sumsq, wc,
                                                    w1a, w1b, w2a, w2b);

    // edge layer 1: h1 = concat(message, x[row]) @ w1a   (+stats slot 0)
    gemm_tf32<0><<<EE / 128, 256, 65536>>>(message, x, row, nullptr,
                                           nullptr, nullptr, nullptr, nullptr, 0.f,
                                           wc, h1, EE, sum + 0, sumsq + 0);

    // edge layer 2: h2 = relu(bn1a(h1)) @ w1b            (+stats slot 1)
    gemm_tf32<1><<<EE / 128, 256, 65536>>>(h1, nullptr, nullptr, nullptr,
                                           sum + 0, sumsq + 0, g1a, be1a, 1.0f / EE,
                                           wc + 32768, h2, EE, sum + 128, sumsq + 128);

    // scatter-mean numerator + counts (bn1b+relu fused, div fused into next gemm)
    scatter_kernel<<<EE / 8, 256>>>(h2, col, sum + 128, sumsq + 128, g1b, be1b,
                                    agg, cnt);

    // node layer 1: o1 = concat(x, agg/cnt) @ w2a        (+stats slot 2)
    gemm_tf32<2><<<(NN + 127) / 128, 256, 65536>>>(x, agg, nullptr, cnt,
                                           nullptr, nullptr, nullptr, nullptr, 0.f,
                                           wc + 49152, o1, NN, sum + 256, sumsq + 256);

    // node layer 2: o2 = relu(bn2a(o1)) @ w2b            (+stats slot 3)
    gemm_tf32<1><<<(NN + 127) / 128, 256, 65536>>>(o1, nullptr, nullptr, nullptr,
                                           sum + 256, sumsq + 256, g2a, be2a, 1.0f / NN,
                                           wc + 81920, o2, NN, sum + 384, sumsq + 384);

    // output: o (N*128 floats) then attn (N floats)
    output_kernel<<<NN, 128>>>(o2, sum + 384, sumsq + 384, g2b, be2b, wa, ba, out);
}

// round 4
// speedup vs baseline: 1.7494x; 1.1086x over previous
#include <cuda_runtime.h>
#include <cuda_fp16.h>
#include <cstdint>
#include <cmath>

// Problem constants (fixed by the dataset)
#define EE 800000
#define NN 50000
#define BN_EPS 1e-5f

// ---------------------------------------------------------------------------
// Scratch (device globals; no runtime allocation)
// ---------------------------------------------------------------------------
__device__ __align__(16) __half g_h1[(size_t)EE * 128];
__device__ __align__(16) __half g_h2[(size_t)EE * 128];
__device__ __align__(16) __half g_o1[(size_t)NN * 128];
__device__ __align__(16) __half g_o2[(size_t)NN * 128];
__device__ float g_agg[(size_t)NN * 128];
__device__ int   g_cnt[NN];
__device__ float g_sum  [512];                  // 4 layers x 128 col sums
__device__ float g_sumsq[512];                  // 4 layers x 128 col sumsq
__device__ __align__(16) __half g_wt16[98304];  // transposed fp16 weights

// ---------------------------------------------------------------------------
// Helpers
// ---------------------------------------------------------------------------
__device__ __forceinline__ uint32_t packh2(float a, float b) {
    __half2 h = __floats2half2_rn(a, b);
    return *(uint32_t*)&h;
}

__device__ __forceinline__ uint32_t smem_u32(const void* p) {
    return (uint32_t)__cvta_generic_to_shared(p);
}

__device__ __forceinline__ void cp_async16(uint32_t dst, const void* src) {
    asm volatile("cp.async.cg.shared.global [%0], [%1], 16;"
                 :: "r"(dst), "l"(src));
}
__device__ __forceinline__ void cp_commit() {
    asm volatile("cp.async.commit_group;" ::: "memory");
}
__device__ __forceinline__ void cp_wait0() {
    asm volatile("cp.async.wait_group 0;" ::: "memory");
}

__device__ __forceinline__ void red_add_v4(float* p, float4 v) {
    asm volatile("red.global.add.v4.f32 [%0], {%1,%2,%3,%4};"
                 :: "l"(p), "f"(v.x), "f"(v.y), "f"(v.z), "f"(v.w) : "memory");
}

// ldmatrix: four 8x8 b16 matrices (non-transposed)
__device__ __forceinline__ void ldsm_x4(uint32_t& r0, uint32_t& r1,
                                        uint32_t& r2, uint32_t& r3,
                                        uint32_t addr) {
    asm volatile("ldmatrix.sync.aligned.m8n8.x4.shared.b16 {%0,%1,%2,%3}, [%4];"
                 : "=r"(r0), "=r"(r1), "=r"(r2), "=r"(r3) : "r"(addr));
}

// mma.m16n8k16 fp16 in, fp32 accumulate
__device__ __forceinline__ void mma_f16(float* c, const uint32_t* a,
                                        uint32_t b0, uint32_t b1) {
    asm volatile(
        "mma.sync.aligned.m16n8k16.row.col.f32.f16.f16.f32 "
        "{%0,%1,%2,%3}, {%4,%5,%6,%7}, {%8,%9}, {%0,%1,%2,%3};"
        : "+f"(c[0]), "+f"(c[1]), "+f"(c[2]), "+f"(c[3])
        : "r"(a[0]), "r"(a[1]), "r"(a[2]), "r"(a[3]), "r"(b0), "r"(b1));
}

// ---------------------------------------------------------------------------
// prep: zero accumulators + transpose/convert weights: Wt16[n][k] = h(W[k][n])
// ---------------------------------------------------------------------------
__global__ void prep_kernel(float* __restrict__ agg, int* __restrict__ cnt,
                            float* __restrict__ sum, float* __restrict__ sumsq,
                            __half* __restrict__ wt,
                            const float* __restrict__ w1a, const float* __restrict__ w1b,
                            const float* __restrict__ w2a, const float* __restrict__ w2b)
{
    int idx = blockIdx.x * blockDim.x + threadIdx.x;
    if (idx < NN * 128) agg[idx] = 0.f;
    if (idx < NN)       cnt[idx] = 0;
    if (idx < 512) { sum[idx] = 0.f; sumsq[idx] = 0.f; }
    if (idx < 98304) {
        float v;
        if (idx < 32768) {                       // w1a: K=256
            int n = idx >> 8, k = idx & 255;
            v = w1a[k * 128 + n];
        } else if (idx < 49152) {                // w1b: K=128
            int i = idx - 32768, n = i >> 7, k = i & 127;
            v = w1b[k * 128 + n];
        } else if (idx < 81920) {                // w2a: K=256
            int i = idx - 49152, n = i >> 8, k = i & 255;
            v = w2a[k * 128 + n];
        } else {                                 // w2b: K=128
            int i = idx - 81920, n = i >> 7, k = i & 127;
            v = w2b[k * 128 + n];
        }
        wt[idx] = __float2half_rn(v);
    }
}

// ---------------------------------------------------------------------------
// fp16 tensor-core GEMM: out[M,128] = A[M,K] @ W[K,128], fused BN-stat epilogue.
// MODE 0: A = concat(message, x[row])      (K=256, f32 sources)
// MODE 1: A = relu(prev*scale + shift)     (K=128, f16 source; scale/shift
//                                           derived in-kernel from prev stats)
// MODE 2: A = concat(x, agg_sum*inv_cnt)   (K=256, f32 sources)
// CTA tile 128x128, K chunked by 64 (A/B fp16 tiles, 128B rows, XOR16 swizzle),
// B staged with cp.async (pre-converted fp16 weights), A staged LDG->cvt->STS
// with invalid rows staged as exact zeros (keeps fused stats exact).
// Fragments via ldmatrix.x4; mma.m16n8k16; epilogue via smem for coalesced
// fp16 stores + warp-shuffle column stats.
// ---------------------------------------------------------------------------
template<int MODE>
__launch_bounds__(256, 2)
__global__ void gemm_f16(
    const float*  __restrict__ A0f,   // mode0: message; mode2: x
    const float*  __restrict__ A1f,   // mode0: x; mode2: agg sums
    const __half* __restrict__ A0h,   // mode1: prev activations (f16)
    const int*    __restrict__ ridx,  // mode0: edge row indices
    const int*    __restrict__ cnt,   // mode2: per-node counts
    const float*  __restrict__ psum,  // mode1: prev-layer col sums
    const float*  __restrict__ psq,   // mode1: prev-layer col sumsq
    const float*  __restrict__ gamma, // mode1
    const float*  __restrict__ beta,  // mode1
    float         invPrevM,           // mode1
    const __half* __restrict__ Wt,    // [128][K] fp16, K-major rows
    __half* __restrict__ Hout,        // [M,128] fp16
    int M,
    float* __restrict__ osum,         // this layer's col-sum slot
    float* __restrict__ osq)          // this layer's col-sumsq slot
{
    constexpr int K   = (MODE == 1) ? 128 : 256;
    constexpr int NIT = K / 64;

    extern __shared__ char dyns[];
    const uint32_t raw   = smem_u32(dyns);
    const uint32_t sbase = (raw + 1023u) & ~1023u;
    char* gbase = dyns + (sbase - raw);
    // layout (fp16 tiles, 128 rows x 64 k = 16KB each):
    // A buf0 @0, A buf1 @16384, B buf0 @32768, B buf1 @49152
    // epilogue staging (128x128 f16 = 32KB) reuses A buffers.

    __shared__ int   sRow[128];
    __shared__ float sInv[128], sScl[128], sSft[128];
    __shared__ float sSum[128], sSq[128];

    const int tid  = threadIdx.x;
    const int warp = tid >> 5;
    const int lane = tid & 31;
    const int bm   = blockIdx.x * 128;

    if (tid < 128) { sSum[tid] = 0.f; sSq[tid] = 0.f; }
    if (MODE == 0 && tid < 128) sRow[tid] = ridx[bm + tid];
    if (MODE == 2 && tid < 128) {
        int r = bm + tid;
        int c = (r < M) ? cnt[r] : 1;
        sInv[tid] = 1.0f / (float)(c > 1 ? c : 1);
    }
    if (MODE == 1 && tid < 128) {
        float m  = psum[tid] * invPrevM;
        float v  = fmaxf(psq[tid] * invPrevM - m * m, 0.f);
        float sc = gamma[tid] * rsqrtf(v + BN_EPS);
        sScl[tid] = sc;
        sSft[tid] = beta[tid] - m * sc;
    }
    __syncthreads();

    // ---- staging: A (LDG f32/f16 -> transform -> f16 STS), B (cp.async) ----
    auto stage = [&](int it, int s) {
        const int k0 = it * 64;
        const uint32_t aB = sbase + (uint32_t)s * 16384u;
        const uint32_t bB = sbase + 32768u + (uint32_t)s * 16384u;
#pragma unroll
        for (int j = 0; j < 4; j++) {
            int u    = tid + j * 256;
            int row  = u >> 3;
            int unit = u & 7;
            int kg   = k0 + unit * 8;
            uint32_t dst = aB + (uint32_t)(row * 128 + ((unit ^ (row & 7)) << 4));
            uint4 o;
            if (MODE == 0) {
                const float* src = (kg < 128)
                    ? (A0f + (size_t)(bm + row) * 128 + kg)
                    : (A1f + (size_t)sRow[row] * 128 + (kg - 128));
                float4 p = *(const float4*)src;
                float4 q = *(const float4*)(src + 4);
                o.x = packh2(p.x, p.y); o.y = packh2(p.z, p.w);
                o.z = packh2(q.x, q.y); o.w = packh2(q.z, q.w);
            } else if (MODE == 1) {
                int rg = bm + row;
                if (rg < M) {
                    uint4 rawv = *(const uint4*)(A0h + (size_t)rg * 128 + kg);
                    float4 sc0 = *(const float4*)(sScl + kg);
                    float4 sc1 = *(const float4*)(sScl + kg + 4);
                    float4 sf0 = *(const float4*)(sSft + kg);
                    float4 sf1 = *(const float4*)(sSft + kg + 4);
                    float2 v0 = __half22float2(*(__half2*)&rawv.x);
                    float2 v1 = __half22float2(*(__half2*)&rawv.y);
                    float2 v2 = __half22float2(*(__half2*)&rawv.z);
                    float2 v3 = __half22float2(*(__half2*)&rawv.w);
                    o.x = packh2(fmaxf(fmaf(v0.x, sc0.x, sf0.x), 0.f),
                                 fmaxf(fmaf(v0.y, sc0.y, sf0.y), 0.f));
                    o.y = packh2(fmaxf(fmaf(v1.x, sc0.z, sf0.z), 0.f),
                                 fmaxf(fmaf(v1.y, sc0.w, sf0.w), 0.f));
                    o.z = packh2(fmaxf(fmaf(v2.x, sc1.x, sf1.x), 0.f),
                                 fmaxf(fmaf(v2.y, sc1.y, sf1.y), 0.f));
                    o.w = packh2(fmaxf(fmaf(v3.x, sc1.z, sf1.z), 0.f),
                                 fmaxf(fmaf(v3.y, sc1.w, sf1.w), 0.f));
                } else {
                    o = make_uint4(0, 0, 0, 0);
                }
            } else { // MODE 2
                int rg = bm + row;
                if (rg < M) {
                    float4 p, q;
                    if (kg < 128) {
                        const float* src = A0f + (size_t)rg * 128 + kg;
                        p = *(const float4*)src; q = *(const float4*)(src + 4);
                    } else {
                        const float* src = A1f + (size_t)rg * 128 + (kg - 128);
                        p = *(const float4*)src; q = *(const float4*)(src + 4);
                        float iv = sInv[row];
                        p.x *= iv; p.y *= iv; p.z *= iv; p.w *= iv;
                        q.x *= iv; q.y *= iv; q.z *= iv; q.w *= iv;
                    }
                    o.x = packh2(p.x, p.y); o.y = packh2(p.z, p.w);
                    o.z = packh2(q.x, q.y); o.w = packh2(q.z, q.w);
                } else {
                    o = make_uint4(0, 0, 0, 0);
                }
            }
            asm volatile("st.shared.v4.b32 [%0], {%1,%2,%3,%4};"
                         :: "r"(dst), "r"(o.x), "r"(o.y), "r"(o.z), "r"(o.w));
        }
        // B: cp.async 16B units from pre-converted fp16 weights
#pragma unroll
        for (int j = 0; j < 4; j++) {
            int u    = tid + j * 256;
            int n    = u >> 3;
            int unit = u & 7;
            uint32_t dst = bB + (uint32_t)(n * 128 + ((unit ^ (n & 7)) << 4));
            cp_async16(dst, Wt + (size_t)n * K + k0 + unit * 8);
        }
        cp_commit();
    };

    float acc[2][8][4];
#pragma unroll
    for (int mi = 0; mi < 2; mi++)
#pragma unroll
        for (int ni = 0; ni < 8; ni++)
#pragma unroll
            for (int v = 0; v < 4; v++) acc[mi][ni][v] = 0.0f;

    const int g   = lane >> 2;
    const int t4  = lane & 3;
    const int wm  = warp & 3;
    const int wn  = warp >> 2;
    const int wr  = wm * 32;
    const int wcc = wn * 64;

    // ldmatrix per-lane row indices (fixed across chunk/step)
    int rA[2], rB[4];
#pragma unroll
    for (int mi = 0; mi < 2; mi++)
        rA[mi] = wr + mi * 16 + (lane & 7) + ((lane >> 3) & 1) * 8;
#pragma unroll
    for (int p = 0; p < 4; p++)
        rB[p] = wcc + p * 16 + (lane & 7) + ((lane >> 3) & 1) * 8;
    const int uHi = (lane >> 4);   // +8 k-offset selector within ldmatrix.x4

    stage(0, 0);

#pragma unroll 1
    for (int it = 0; it < NIT; it++) {
        const int s = it & 1;
        cp_wait0();
        __syncthreads();
        if (it + 1 < NIT) stage(it + 1, s ^ 1);

        const uint32_t aB = sbase + (uint32_t)s * 16384u;
        const uint32_t bB = sbase + 32768u + (uint32_t)s * 16384u;

#pragma unroll
        for (int step = 0; step < 4; step++) {
            const int unit = step * 2 + uHi;
            uint32_t a[2][4];
#pragma unroll
            for (int mi = 0; mi < 2; mi++)
                ldsm_x4(a[mi][0], a[mi][1], a[mi][2], a[mi][3],
                        aB + (uint32_t)(rA[mi] * 128 + ((unit ^ (rA[mi] & 7)) << 4)));
#pragma unroll
            for (int p = 0; p < 4; p++) {
                uint32_t b0, b1, b2, b3;
                ldsm_x4(b0, b1, b2, b3,
                        bB + (uint32_t)(rB[p] * 128 + ((unit ^ (rB[p] & 7)) << 4)));
#pragma unroll
                for (int mi = 0; mi < 2; mi++) {
                    mma_f16(acc[mi][2 * p],     a[mi], b0, b2);
                    mma_f16(acc[mi][2 * p + 1], a[mi], b1, b3);
                }
            }
        }
        __syncthreads();   // protect buffer s before it is restaged (it+2)
    }

    // ---- fused BN-stat reduction (padded rows are exact zeros) ----
#pragma unroll
    for (int ni = 0; ni < 8; ni++) {
        float s0 = 0, q0 = 0, s1 = 0, q1 = 0;
#pragma unroll
        for (int mi = 0; mi < 2; mi++) {
            float a0 = acc[mi][ni][0], a2 = acc[mi][ni][2];
            float a1 = acc[mi][ni][1], a3 = acc[mi][ni][3];
            s0 += a0 + a2; q0 += a0 * a0 + a2 * a2;
            s1 += a1 + a3; q1 += a1 * a1 + a3 * a3;
        }
#pragma unroll
        for (int off = 4; off < 32; off <<= 1) {
            s0 += __shfl_xor_sync(0xFFFFFFFFu, s0, off);
            q0 += __shfl_xor_sync(0xFFFFFFFFu, q0, off);
            s1 += __shfl_xor_sync(0xFFFFFFFFu, s1, off);
            q1 += __shfl_xor_sync(0xFFFFFFFFu, q1, off);
        }
        if (lane < 4) {
            int c0 = wcc + ni * 8 + 2 * t4;
            atomicAdd(&sSum[c0],     s0); atomicAdd(&sSq[c0],     q0);
            atomicAdd(&sSum[c0 + 1], s1); atomicAdd(&sSq[c0 + 1], q1);
        }
    }

    // ---- epilogue: acc -> f16 via smem (swizzled), then coalesced STG ----
    __syncthreads();                     // all mma reads of A buffers done
    char* epi = gbase;                   // 128 x 256B fp16 rows
#pragma unroll
    for (int mi = 0; mi < 2; mi++) {
        int r0 = wr + mi * 16 + g;
        int r1 = r0 + 8;
#pragma unroll
        for (int ni = 0; ni < 8; ni++) {
            int col = wcc + ni * 8 + 2 * t4;
            *(uint32_t*)(epi + r0 * 256 + ((col * 2) ^ ((r0 & 7) << 5))) =
                packh2(acc[mi][ni][0], acc[mi][ni][1]);
            *(uint32_t*)(epi + r1 * 256 + ((col * 2) ^ ((r1 & 7) << 5))) =
                packh2(acc[mi][ni][2], acc[mi][ni][3]);
        }
    }
    __syncthreads();
#pragma unroll
    for (int i = 0; i < 8; i++) {
        int gid = tid + i * 256;
        int row = gid >> 4;
        int seg = gid & 15;
        if (bm + row < M) {
            uint4 v = *(uint4*)(epi + row * 256 + ((seg * 16) ^ ((row & 7) << 5)));
            *(uint4*)(Hout + (size_t)(bm + row) * 128 + seg * 8) = v;
        }
    }

    if (tid < 128) {
        atomicAdd(osum + tid, sSum[tid]);
        atomicAdd(osq  + tid, sSq[tid]);
    }
}

// ---------------------------------------------------------------------------
// Scatter: agg[col[e]] += relu(bn(h2_f16[e])), cnt[col[e]] += 1 (warp/edge)
// ---------------------------------------------------------------------------
__global__ void scatter_kernel(const __half* __restrict__ h2,
                               const int* __restrict__ col,
                               const float* __restrict__ psum,
                               const float* __restrict__ psq,
                               const float* __restrict__ gamma,
                               const float* __restrict__ beta,
                               float* __restrict__ agg, int* __restrict__ cnt)
{
    __shared__ float sScl[128], sSft[128];
    int t = threadIdx.x;                 // 256
    if (t < 128) {
        float m  = psum[t] * (1.0f / EE);
        float v  = fmaxf(psq[t] * (1.0f / EE) - m * m, 0.f);
        float sc = gamma[t] * rsqrtf(v + BN_EPS);
        sScl[t] = sc;
        sSft[t] = beta[t] - m * sc;
    }
    __syncthreads();

    int e    = blockIdx.x * 8 + (t >> 5);
    int lane = t & 31;
    int c    = __ldg(col + e);
    uint2 rawv = *(const uint2*)(h2 + (size_t)e * 128 + lane * 4);
    float2 a = __half22float2(*(__half2*)&rawv.x);
    float2 b = __half22float2(*(__half2*)&rawv.y);
    float4 sc = *(const float4*)(sScl + lane * 4);
    float4 sf = *(const float4*)(sSft + lane * 4);
    float4 v;
    v.x = fmaxf(fmaf(a.x, sc.x, sf.x), 0.f);
    v.y = fmaxf(fmaf(a.y, sc.y, sf.y), 0.f);
    v.z = fmaxf(fmaf(b.x, sc.z, sf.z), 0.f);
    v.w = fmaxf(fmaf(b.y, sc.w, sf.w), 0.f);
    red_add_v4(agg + (size_t)c * 128 + lane * 4, v);
    if (lane == 0) atomicAdd(cnt + c, 1);
}

// ---------------------------------------------------------------------------
// Final: o = relu(bn(o2)); attn = sigmoid(o @ wa + ba)
// ---------------------------------------------------------------------------
__global__ void output_kernel(const __half* __restrict__ o2,
                              const float* __restrict__ psum,
                              const float* __restrict__ psq,
                              const float* __restrict__ gamma,
                              const float* __restrict__ beta,
                              const float* __restrict__ wa,
                              const float* __restrict__ ba,
                              float* __restrict__ out)
{
    __shared__ float red[4];
    int n = blockIdx.x;
    int t = threadIdx.x;                 // 128
    float m  = psum[t] * (1.0f / NN);
    float vv = fmaxf(psq[t] * (1.0f / NN) - m * m, 0.f);
    float sc = gamma[t] * rsqrtf(vv + BN_EPS);
    float sf = beta[t] - m * sc;

    float v = __half2float(o2[(size_t)n * 128 + t]);
    v = fmaxf(fmaf(v, sc, sf), 0.f);
    out[(size_t)n * 128 + t] = v;

    float p = v * wa[t];
#pragma unroll
    for (int off = 16; off > 0; off >>= 1)
        p += __shfl_xor_sync(0xFFFFFFFFu, p, off);
    if ((t & 31) == 0) red[t >> 5] = p;
    __syncthreads();
    if (t == 0) {
        float d = red[0] + red[1] + red[2] + red[3] + ba[0];
        out[(size_t)NN * 128 + n] = 1.0f / (1.0f + expf(-d));
    }
}

// ---------------------------------------------------------------------------
// Launch
// ---------------------------------------------------------------------------
#define GEMM_SMEM (65536 + 1024)

extern "C" void kernel_launch(void* const* d_in, const int* in_sizes, int n_in,
                              void* d_out, int out_size)
{
    const float* x       = (const float*)d_in[0];
    const int*   ei      = (const int*)  d_in[1];   // [2,E]: row then col
    const float* message = (const float*)d_in[2];
    const float* w1a  = (const float*)d_in[3];
    const float* g1a  = (const float*)d_in[5];
    const float* be1a = (const float*)d_in[6];
    const float* w1b  = (const float*)d_in[7];
    const float* g1b  = (const float*)d_in[9];
    const float* be1b = (const float*)d_in[10];
    const float* w2a  = (const float*)d_in[11];
    const float* g2a  = (const float*)d_in[13];
    const float* be2a = (const float*)d_in[14];
    const float* w2b  = (const float*)d_in[15];
    const float* g2b  = (const float*)d_in[17];
    const float* be2b = (const float*)d_in[18];
    const float* wa   = (const float*)d_in[19];
    const float* ba   = (const float*)d_in[20];
    float* out = (float*)d_out;

    __half *h1, *h2, *o1, *o2, *wt;
    float *agg, *sum, *sumsq;
    int* cnt;
    cudaGetSymbolAddress((void**)&h1,    g_h1);
    cudaGetSymbolAddress((void**)&h2,    g_h2);
    cudaGetSymbolAddress((void**)&o1,    g_o1);
    cudaGetSymbolAddress((void**)&o2,    g_o2);
    cudaGetSymbolAddress((void**)&agg,   g_agg);
    cudaGetSymbolAddress((void**)&cnt,   g_cnt);
    cudaGetSymbolAddress((void**)&sum,   g_sum);
    cudaGetSymbolAddress((void**)&sumsq, g_sumsq);
    cudaGetSymbolAddress((void**)&wt,    g_wt16);

    const int* row = ei;
    const int* col = ei + EE;

    static bool attr_done = false;
    if (!attr_done) {
        cudaFuncSetAttribute(gemm_f16<0>, cudaFuncAttributeMaxDynamicSharedMemorySize, GEMM_SMEM);
        cudaFuncSetAttribute(gemm_f16<1>, cudaFuncAttributeMaxDynamicSharedMemorySize, GEMM_SMEM);
        cudaFuncSetAttribute(gemm_f16<2>, cudaFuncAttributeMaxDynamicSharedMemorySize, GEMM_SMEM);
        attr_done = true;
    }

    prep_kernel<<<(NN * 128 + 1023) / 1024, 1024>>>(agg, cnt, sum, sumsq, wt,
                                                    w1a, w1b, w2a, w2b);

    // edge layer 1: h1 = concat(message, x[row]) @ w1a   (+stats slot 0)
    gemm_f16<0><<<EE / 128, 256, GEMM_SMEM>>>(message, x, nullptr, row, nullptr,
                                 nullptr, nullptr, nullptr, nullptr, 0.f,
                                 wt, h1, EE, sum + 0, sumsq + 0);

    // edge layer 2: h2 = relu(bn1a(h1)) @ w1b            (+stats slot 1)
    gemm_f16<1><<<EE / 128, 256, GEMM_SMEM>>>(nullptr, nullptr, h1, nullptr, nullptr,
                                 sum + 0, sumsq + 0, g1a, be1a, 1.0f / EE,
                                 wt + 32768, h2, EE, sum + 128, sumsq + 128);

    // scatter-mean numerator + counts (bn1b+relu fused, div fused into next gemm)
    scatter_kernel<<<EE / 8, 256>>>(h2, col, sum + 128, sumsq + 128, g1b, be1b,
                                    agg, cnt);

    // node layer 1: o1 = concat(x, agg/cnt) @ w2a        (+stats slot 2)
    gemm_f16<2><<<(NN + 127) / 128, 256, GEMM_SMEM>>>(x, agg, nullptr, nullptr, cnt,
                                 nullptr, nullptr, nullptr, nullptr, 0.f,
                                 wt + 49152, o1, NN, sum + 256, sumsq + 256);

    // node layer 2: o2 = relu(bn2a(o1)) @ w2b            (+stats slot 3)
    gemm_f16<1><<<(NN + 127) / 128, 256, GEMM_SMEM>>>(nullptr, nullptr, o1, nullptr, nullptr,
                                 sum + 256, sumsq + 256, g2a, be2a, 1.0f / NN,
                                 wt + 81920, o2, NN, sum + 384, sumsq + 384);

    // output: o (N*128 floats) then attn (N floats)
    output_kernel<<<NN, 128>>>(o2, sum + 384, sumsq + 384, g2b, be2b, wa, ba, out);
}

// round 5
// speedup vs baseline: 2.0207x; 1.1551x over previous
#include <cuda_runtime.h>
#include <cuda_fp16.h>
#include <cstdint>
#include <cmath>

// Problem constants (fixed by the dataset)
#define EE 800000
#define NN 50000
#define BN_EPS 1e-5f

// ---------------------------------------------------------------------------
// Scratch (device globals; no runtime allocation)
// ---------------------------------------------------------------------------
__device__ __align__(16) __half g_h1[(size_t)EE * 128];
__device__ __align__(16) __half g_h2[(size_t)EE * 128];
__device__ __align__(16) __half g_o1[(size_t)NN * 128];
__device__ __align__(16) __half g_o2[(size_t)NN * 128];
__device__ float g_agg[(size_t)NN * 128];
__device__ int   g_cnt[NN];
__device__ float g_sum  [512];                  // 4 layers x 128 col sums
__device__ float g_sumsq[512];                  // 4 layers x 128 col sumsq
__device__ __align__(16) __half g_wt16[98304];  // transposed fp16 weights

// ---------------------------------------------------------------------------
// Helpers
// ---------------------------------------------------------------------------
__device__ __forceinline__ uint32_t packh2(float a, float b) {
    __half2 h = __floats2half2_rn(a, b);
    return *(uint32_t*)&h;
}

__device__ __forceinline__ uint32_t smem_u32(const void* p) {
    return (uint32_t)__cvta_generic_to_shared(p);
}

__device__ __forceinline__ void cp_async16(uint32_t dst, const void* src) {
    asm volatile("cp.async.cg.shared.global [%0], [%1], 16;"
                 :: "r"(dst), "l"(src));
}
__device__ __forceinline__ void cp_commit() {
    asm volatile("cp.async.commit_group;" ::: "memory");
}
__device__ __forceinline__ void cp_wait0() {
    asm volatile("cp.async.wait_group 0;" ::: "memory");
}

__device__ __forceinline__ void red_add_v4(float* p, float4 v) {
    asm volatile("red.global.add.v4.f32 [%0], {%1,%2,%3,%4};"
                 :: "l"(p), "f"(v.x), "f"(v.y), "f"(v.z), "f"(v.w) : "memory");
}

// ldmatrix: four 8x8 b16 matrices (non-transposed)
__device__ __forceinline__ void ldsm_x4(uint32_t& r0, uint32_t& r1,
                                        uint32_t& r2, uint32_t& r3,
                                        uint32_t addr) {
    asm volatile("ldmatrix.sync.aligned.m8n8.x4.shared.b16 {%0,%1,%2,%3}, [%4];"
                 : "=r"(r0), "=r"(r1), "=r"(r2), "=r"(r3) : "r"(addr));
}

// mma.m16n8k16 fp16 in, fp32 accumulate
__device__ __forceinline__ void mma_f16(float* c, const uint32_t* a,
                                        uint32_t b0, uint32_t b1) {
    asm volatile(
        "mma.sync.aligned.m16n8k16.row.col.f32.f16.f16.f32 "
        "{%0,%1,%2,%3}, {%4,%5,%6,%7}, {%8,%9}, {%0,%1,%2,%3};"
        : "+f"(c[0]), "+f"(c[1]), "+f"(c[2]), "+f"(c[3])
        : "r"(a[0]), "r"(a[1]), "r"(a[2]), "r"(a[3]), "r"(b0), "r"(b1));
}

__device__ __forceinline__ void sts_v4(uint32_t dst, uint4 o) {
    asm volatile("st.shared.v4.b32 [%0], {%1,%2,%3,%4};"
                 :: "r"(dst), "r"(o.x), "r"(o.y), "r"(o.z), "r"(o.w));
}

// ---------------------------------------------------------------------------
// prep: zero accumulators + transpose/convert weights: Wt16[n][k] = h(W[k][n])
// ---------------------------------------------------------------------------
__global__ void prep_kernel(float* __restrict__ agg, int* __restrict__ cnt,
                            float* __restrict__ sum, float* __restrict__ sumsq,
                            __half* __restrict__ wt,
                            const float* __restrict__ w1a, const float* __restrict__ w1b,
                            const float* __restrict__ w2a, const float* __restrict__ w2b)
{
    int idx = blockIdx.x * blockDim.x + threadIdx.x;
    if (idx < NN * 128) agg[idx] = 0.f;
    if (idx < NN)       cnt[idx] = 0;
    if (idx < 512) { sum[idx] = 0.f; sumsq[idx] = 0.f; }
    if (idx < 98304) {
        float v;
        if (idx < 32768) {                       // w1a: K=256
            int n = idx >> 8, k = idx & 255;
            v = w1a[k * 128 + n];
        } else if (idx < 49152) {                // w1b: K=128
            int i = idx - 32768, n = i >> 7, k = i & 127;
            v = w1b[k * 128 + n];
        } else if (idx < 81920) {                // w2a: K=256
            int i = idx - 49152, n = i >> 8, k = i & 255;
            v = w2a[k * 128 + n];
        } else {                                 // w2b: K=128
            int i = idx - 81920, n = i >> 7, k = i & 127;
            v = w2b[k * 128 + n];
        }
        wt[idx] = __float2half_rn(v);
    }
}

// ---------------------------------------------------------------------------
// fp16 tensor-core GEMM: out[M,128] = A[M,K] @ W[K,128], fused BN-stat epilogue.
// MODE 0: A = concat(message, x[row])      (K=256, f32 sources)
// MODE 1: A = relu(prev*scale + shift)     (K=128, f16 source)
// MODE 2: A = concat(x, agg_sum*inv_cnt)   (K=256, f32 sources)
// Register-software-pipelined A path: raw LDGs for chunk it+1 are issued
// BEFORE chunk it's MMA block and consumed (transform+pack+STS) after it, so
// load latency hides behind tensor work. B via cp.async (fp16 weights).
// Invalid rows are forced to exact zeros AFTER the affine (exact fused stats).
// ---------------------------------------------------------------------------
template<int MODE>
__launch_bounds__(256, 2)
__global__ void gemm_f16(
    const float*  __restrict__ A0f,   // mode0: message; mode2: x
    const float*  __restrict__ A1f,   // mode0: x; mode2: agg sums
    const __half* __restrict__ A0h,   // mode1: prev activations (f16)
    const int*    __restrict__ ridx,  // mode0: edge row indices
    const int*    __restrict__ cnt,   // mode2: per-node counts
    const float*  __restrict__ psum,  // mode1: prev-layer col sums
    const float*  __restrict__ psq,   // mode1: prev-layer col sumsq
    const float*  __restrict__ gamma, // mode1
    const float*  __restrict__ beta,  // mode1
    float         invPrevM,           // mode1
    const __half* __restrict__ Wt,    // [128][K] fp16, K-major rows
    __half* __restrict__ Hout,        // [M,128] fp16
    int M,
    float* __restrict__ osum,         // this layer's col-sum slot
    float* __restrict__ osq)          // this layer's col-sumsq slot
{
    constexpr int K   = (MODE == 1) ? 128 : 256;
    constexpr int NIT = K / 64;

    extern __shared__ char dyns[];
    const uint32_t raw   = smem_u32(dyns);
    const uint32_t sbase = (raw + 1023u) & ~1023u;
    char* gbase = dyns + (sbase - raw);
    // layout (fp16 tiles, 128 rows x 64 k = 16KB each):
    // A buf0 @0, A buf1 @16384, B buf0 @32768, B buf1 @49152
    // epilogue staging (128x128 f16 = 32KB) reuses A buffers.

    __shared__ int   sRow[128];
    __shared__ float sInv[128], sScl[128], sSft[128];
    __shared__ float sSum[128], sSq[128];

    const int tid  = threadIdx.x;
    const int warp = tid >> 5;
    const int lane = tid & 31;
    const int bm   = blockIdx.x * 128;

    if (tid < 128) { sSum[tid] = 0.f; sSq[tid] = 0.f; }
    if (MODE == 0 && tid < 128) sRow[tid] = ridx[bm + tid];
    if (MODE == 2 && tid < 128) {
        int r = bm + tid;
        int c = (r < M) ? cnt[r] : 1;
        sInv[tid] = 1.0f / (float)(c > 1 ? c : 1);
    }
    if (MODE == 1 && tid < 128) {
        float m  = psum[tid] * invPrevM;
        float v  = fmaxf(psq[tid] * invPrevM - m * m, 0.f);
        float sc = gamma[tid] * rsqrtf(v + BN_EPS);
        sScl[tid] = sc;
        sSft[tid] = beta[tid] - m * sc;
    }
    __syncthreads();

    // ---- raw A loads for chunk it (no transform; pure LDG issue) ----
    auto ldgA = [&](int it, float4* pf, uint4* ph) {
        const int k0 = it * 64;
#pragma unroll
        for (int j = 0; j < 4; j++) {
            int u = tid + j * 256, row = u >> 3, unit = u & 7;
            int kg = k0 + unit * 8;
            int rg = bm + row;
            if (MODE == 1) {
                ph[j] = (rg < M) ? *(const uint4*)(A0h + (size_t)rg * 128 + kg)
                                 : make_uint4(0, 0, 0, 0);
            } else if (MODE == 0) {
                const float* src = (kg < 128)
                    ? (A0f + (size_t)rg * 128 + kg)
                    : (A1f + (size_t)sRow[row] * 128 + (kg - 128));
                pf[2 * j]     = *(const float4*)src;
                pf[2 * j + 1] = *(const float4*)(src + 4);
            } else { // MODE 2
                if (rg < M) {
                    const float* src = (kg < 128)
                        ? (A0f + (size_t)rg * 128 + kg)
                        : (A1f + (size_t)rg * 128 + (kg - 128));
                    pf[2 * j]     = *(const float4*)src;
                    pf[2 * j + 1] = *(const float4*)(src + 4);
                } else {
                    pf[2 * j]     = make_float4(0, 0, 0, 0);
                    pf[2 * j + 1] = make_float4(0, 0, 0, 0);
                }
            }
        }
    };

    // ---- transform + pack + STS for chunk it into buffer s ----
    auto stsA = [&](int it, int s, const float4* pf, const uint4* ph) {
        const int k0 = it * 64;
        const uint32_t aB = sbase + (uint32_t)s * 16384u;
#pragma unroll
        for (int j = 0; j < 4; j++) {
            int u = tid + j * 256, row = u >> 3, unit = u & 7;
            int kg = k0 + unit * 8;
            int rg = bm + row;
            uint32_t dst = aB + (uint32_t)(row * 128 + ((unit ^ (row & 7)) << 4));
            uint4 o;
            if (MODE == 0) {
                float4 p = pf[2 * j], q = pf[2 * j + 1];
                o.x = packh2(p.x, p.y); o.y = packh2(p.z, p.w);
                o.z = packh2(q.x, q.y); o.w = packh2(q.z, q.w);
            } else if (MODE == 1) {
                if (rg < M) {
                    uint4 rv = ph[j];
                    float4 sc0 = *(const float4*)(sScl + kg);
                    float4 sc1 = *(const float4*)(sScl + kg + 4);
                    float4 sf0 = *(const float4*)(sSft + kg);
                    float4 sf1 = *(const float4*)(sSft + kg + 4);
                    float2 v0 = __half22float2(*(__half2*)&rv.x);
                    float2 v1 = __half22float2(*(__half2*)&rv.y);
                    float2 v2 = __half22float2(*(__half2*)&rv.z);
                    float2 v3 = __half22float2(*(__half2*)&rv.w);
                    o.x = packh2(fmaxf(fmaf(v0.x, sc0.x, sf0.x), 0.f),
                                 fmaxf(fmaf(v0.y, sc0.y, sf0.y), 0.f));
                    o.y = packh2(fmaxf(fmaf(v1.x, sc0.z, sf0.z), 0.f),
                                 fmaxf(fmaf(v1.y, sc0.w, sf0.w), 0.f));
                    o.z = packh2(fmaxf(fmaf(v2.x, sc1.x, sf1.x), 0.f),
                                 fmaxf(fmaf(v2.y, sc1.y, sf1.y), 0.f));
                    o.w = packh2(fmaxf(fmaf(v3.x, sc1.z, sf1.z), 0.f),
                                 fmaxf(fmaf(v3.y, sc1.w, sf1.w), 0.f));
                } else {
                    o = make_uint4(0, 0, 0, 0);
                }
            } else { // MODE 2
                if (rg < M) {
                    float4 p = pf[2 * j], q = pf[2 * j + 1];
                    if (kg >= 128) {
                        float iv = sInv[row];
                        p.x *= iv; p.y *= iv; p.z *= iv; p.w *= iv;
                        q.x *= iv; q.y *= iv; q.z *= iv; q.w *= iv;
                    }
                    o.x = packh2(p.x, p.y); o.y = packh2(p.z, p.w);
                    o.z = packh2(q.x, q.y); o.w = packh2(q.z, q.w);
                } else {
                    o = make_uint4(0, 0, 0, 0);
                }
            }
            sts_v4(dst, o);
        }
    };

    // ---- B staging via cp.async (pre-converted fp16 weights) ----
    auto cpB = [&](int it, int s) {
        const int k0 = it * 64;
        const uint32_t bB = sbase + 32768u + (uint32_t)s * 16384u;
#pragma unroll
        for (int j = 0; j < 4; j++) {
            int u = tid + j * 256, n = u >> 3, unit = u & 7;
            uint32_t dst = bB + (uint32_t)(n * 128 + ((unit ^ (n & 7)) << 4));
            cp_async16(dst, Wt + (size_t)n * K + k0 + unit * 8);
        }
        cp_commit();
    };

    float acc[2][8][4];
#pragma unroll
    for (int mi = 0; mi < 2; mi++)
#pragma unroll
        for (int ni = 0; ni < 8; ni++)
#pragma unroll
            for (int v = 0; v < 4; v++) acc[mi][ni][v] = 0.0f;

    const int g   = lane >> 2;
    const int t4  = lane & 3;
    const int wm  = warp & 3;
    const int wn  = warp >> 2;
    const int wr  = wm * 32;
    const int wcc = wn * 64;

    // ldmatrix per-lane row indices (fixed across chunk/step)
    int rA[2], rB[4];
#pragma unroll
    for (int mi = 0; mi < 2; mi++)
        rA[mi] = wr + mi * 16 + (lane & 7) + ((lane >> 3) & 1) * 8;
#pragma unroll
    for (int p = 0; p < 4; p++)
        rB[p] = wcc + p * 16 + (lane & 7) + ((lane >> 3) & 1) * 8;
    const int uHi = (lane >> 4);   // +8 k-offset selector within ldmatrix.x4

    // ---- prologue: chunk 0 staged synchronously ----
    {
        float4 pf[8]; uint4 ph[4];
        ldgA(0, pf, ph);
        stsA(0, 0, pf, ph);
        cpB(0, 0);
    }

#pragma unroll 1
    for (int it = 0; it < NIT; it++) {
        const int s = it & 1;
        cp_wait0();            // B(it) arrived (only group in flight)
        __syncthreads();       // A(it) STS visible; all warps done chunk it-1

        float4 pf[8]; uint4 ph[4];
        const bool more = (it + 1 < NIT);
        if (more) {
            ldgA(it + 1, pf, ph);   // raw loads issued BEFORE compute
            cpB(it + 1, s ^ 1);
        }

        const uint32_t aB = sbase + (uint32_t)s * 16384u;
        const uint32_t bB = sbase + 32768u + (uint32_t)s * 16384u;

#pragma unroll
        for (int step = 0; step < 4; step++) {
            const int unit = step * 2 + uHi;
            uint32_t a[2][4];
#pragma unroll
            for (int mi = 0; mi < 2; mi++)
                ldsm_x4(a[mi][0], a[mi][1], a[mi][2], a[mi][3],
                        aB + (uint32_t)(rA[mi] * 128 + ((unit ^ (rA[mi] & 7)) << 4)));
#pragma unroll
            for (int p = 0; p < 4; p++) {
                uint32_t b0, b1, b2, b3;
                ldsm_x4(b0, b1, b2, b3,
                        bB + (uint32_t)(rB[p] * 128 + ((unit ^ (rB[p] & 7)) << 4)));
#pragma unroll
                for (int mi = 0; mi < 2; mi++) {
                    mma_f16(acc[mi][2 * p],     a[mi], b0, b2);
                    mma_f16(acc[mi][2 * p + 1], a[mi], b1, b3);
                }
            }
        }

        if (more) stsA(it + 1, s ^ 1, pf, ph);  // consume raw loads after MMA
    }

    // ---- fused BN-stat reduction (padded rows are exact zeros) ----
#pragma unroll
    for (int ni = 0; ni < 8; ni++) {
        float s0 = 0, q0 = 0, s1 = 0, q1 = 0;
#pragma unroll
        for (int mi = 0; mi < 2; mi++) {
            float a0 = acc[mi][ni][0], a2 = acc[mi][ni][2];
            float a1 = acc[mi][ni][1], a3 = acc[mi][ni][3];
            s0 += a0 + a2; q0 += a0 * a0 + a2 * a2;
            s1 += a1 + a3; q1 += a1 * a1 + a3 * a3;
        }
#pragma unroll
        for (int off = 4; off < 32; off <<= 1) {
            s0 += __shfl_xor_sync(0xFFFFFFFFu, s0, off);
            q0 += __shfl_xor_sync(0xFFFFFFFFu, q0, off);
            s1 += __shfl_xor_sync(0xFFFFFFFFu, s1, off);
            q1 += __shfl_xor_sync(0xFFFFFFFFu, q1, off);
        }
        if (lane < 4) {
            int c0 = wcc + ni * 8 + 2 * t4;
            atomicAdd(&sSum[c0],     s0); atomicAdd(&sSq[c0],     q0);
            atomicAdd(&sSum[c0 + 1], s1); atomicAdd(&sSq[c0 + 1], q1);
        }
    }

    // ---- epilogue: acc -> f16 via smem (swizzled), then coalesced STG ----
    __syncthreads();                     // all ldmatrix reads of A/B done
    char* epi = gbase;                   // 128 x 256B fp16 rows
#pragma unroll
    for (int mi = 0; mi < 2; mi++) {
        int r0 = wr + mi * 16 + g;
        int r1 = r0 + 8;
#pragma unroll
        for (int ni = 0; ni < 8; ni++) {
            int col = wcc + ni * 8 + 2 * t4;
            *(uint32_t*)(epi + r0 * 256 + ((col * 2) ^ ((r0 & 7) << 5))) =
                packh2(acc[mi][ni][0], acc[mi][ni][1]);
            *(uint32_t*)(epi + r1 * 256 + ((col * 2) ^ ((r1 & 7) << 5))) =
                packh2(acc[mi][ni][2], acc[mi][ni][3]);
        }
    }
    __syncthreads();
#pragma unroll
    for (int i = 0; i < 8; i++) {
        int gid = tid + i * 256;
        int row = gid >> 4;
        int seg = gid & 15;
        if (bm + row < M) {
            uint4 v = *(uint4*)(epi + row * 256 + ((seg * 16) ^ ((row & 7) << 5)));
            *(uint4*)(Hout + (size_t)(bm + row) * 128 + seg * 8) = v;
        }
    }

    if (tid < 128) {
        atomicAdd(osum + tid, sSum[tid]);
        atomicAdd(osq  + tid, sSq[tid]);
    }
}

// ---------------------------------------------------------------------------
// Scatter: agg[col[e]] += relu(bn(h2_f16[e])), cnt[col[e]] += 1 (warp/edge)
// ---------------------------------------------------------------------------
__global__ void scatter_kernel(const __half* __restrict__ h2,
                               const int* __restrict__ col,
                               const float* __restrict__ psum,
                               const float* __restrict__ psq,
                               const float* __restrict__ gamma,
                               const float* __restrict__ beta,
                               float* __restrict__ agg, int* __restrict__ cnt)
{
    __shared__ float sScl[128], sSft[128];
    int t = threadIdx.x;                 // 256
    if (t < 128) {
        float m  = psum[t] * (1.0f / EE);
        float v  = fmaxf(psq[t] * (1.0f / EE) - m * m, 0.f);
        float sc = gamma[t] * rsqrtf(v + BN_EPS);
        sScl[t] = sc;
        sSft[t] = beta[t] - m * sc;
    }
    __syncthreads();

    int e    = blockIdx.x * 8 + (t >> 5);
    int lane = t & 31;
    int c    = __ldg(col + e);
    uint2 rawv = *(const uint2*)(h2 + (size_t)e * 128 + lane * 4);
    float2 a = __half22float2(*(__half2*)&rawv.x);
    float2 b = __half22float2(*(__half2*)&rawv.y);
    float4 sc = *(const float4*)(sScl + lane * 4);
    float4 sf = *(const float4*)(sSft + lane * 4);
    float4 v;
    v.x = fmaxf(fmaf(a.x, sc.x, sf.x), 0.f);
    v.y = fmaxf(fmaf(a.y, sc.y, sf.y), 0.f);
    v.z = fmaxf(fmaf(b.x, sc.z, sf.z), 0.f);
    v.w = fmaxf(fmaf(b.y, sc.w, sf.w), 0.f);
    red_add_v4(agg + (size_t)c * 128 + lane * 4, v);
    if (lane == 0) atomicAdd(cnt + c, 1);
}

// ---------------------------------------------------------------------------
// Final: o = relu(bn(o2)); attn = sigmoid(o @ wa + ba)
// ---------------------------------------------------------------------------
__global__ void output_kernel(const __half* __restrict__ o2,
                              const float* __restrict__ psum,
                              const float* __restrict__ psq,
                              const float* __restrict__ gamma,
                              const float* __restrict__ beta,
                              const float* __restrict__ wa,
                              const float* __restrict__ ba,
                              float* __restrict__ out)
{
    __shared__ float red[4];
    int n = blockIdx.x;
    int t = threadIdx.x;                 // 128
    float m  = psum[t] * (1.0f / NN);
    float vv = fmaxf(psq[t] * (1.0f / NN) - m * m, 0.f);
    float sc = gamma[t] * rsqrtf(vv + BN_EPS);
    float sf = beta[t] - m * sc;

    float v = __half2float(o2[(size_t)n * 128 + t]);
    v = fmaxf(fmaf(v, sc, sf), 0.f);
    out[(size_t)n * 128 + t] = v;

    float p = v * wa[t];
#pragma unroll
    for (int off = 16; off > 0; off >>= 1)
        p += __shfl_xor_sync(0xFFFFFFFFu, p, off);
    if ((t & 31) == 0) red[t >> 5] = p;
    __syncthreads();
    if (t == 0) {
        float d = red[0] + red[1] + red[2] + red[3] + ba[0];
        out[(size_t)NN * 128 + n] = 1.0f / (1.0f + expf(-d));
    }
}

// ---------------------------------------------------------------------------
// Launch
// ---------------------------------------------------------------------------
#define GEMM_SMEM (65536 + 1024)

extern "C" void kernel_launch(void* const* d_in, const int* in_sizes, int n_in,
                              void* d_out, int out_size)
{
    const float* x       = (const float*)d_in[0];
    const int*   ei      = (const int*)  d_in[1];   // [2,E]: row then col
    const float* message = (const float*)d_in[2];
    const float* w1a  = (const float*)d_in[3];
    const float* g1a  = (const float*)d_in[5];
    const float* be1a = (const float*)d_in[6];
    const float* w1b  = (const float*)d_in[7];
    const float* g1b  = (const float*)d_in[9];
    const float* be1b = (const float*)d_in[10];
    const float* w2a  = (const float*)d_in[11];
    const float* g2a  = (const float*)d_in[13];
    const float* be2a = (const float*)d_in[14];
    const float* w2b  = (const float*)d_in[15];
    const float* g2b  = (const float*)d_in[17];
    const float* be2b = (const float*)d_in[18];
    const float* wa   = (const float*)d_in[19];
    const float* ba   = (const float*)d_in[20];
    float* out = (float*)d_out;

    __half *h1, *h2, *o1, *o2, *wt;
    float *agg, *sum, *sumsq;
    int* cnt;
    cudaGetSymbolAddress((void**)&h1,    g_h1);
    cudaGetSymbolAddress((void**)&h2,    g_h2);
    cudaGetSymbolAddress((void**)&o1,    g_o1);
    cudaGetSymbolAddress((void**)&o2,    g_o2);
    cudaGetSymbolAddress((void**)&agg,   g_agg);
    cudaGetSymbolAddress((void**)&cnt,   g_cnt);
    cudaGetSymbolAddress((void**)&sum,   g_sum);
    cudaGetSymbolAddress((void**)&sumsq, g_sumsq);
    cudaGetSymbolAddress((void**)&wt,    g_wt16);

    const int* row = ei;
    const int* col = ei + EE;

    static bool attr_done = false;
    if (!attr_done) {
        cudaFuncSetAttribute(gemm_f16<0>, cudaFuncAttributeMaxDynamicSharedMemorySize, GEMM_SMEM);
        cudaFuncSetAttribute(gemm_f16<1>, cudaFuncAttributeMaxDynamicSharedMemorySize, GEMM_SMEM);
        cudaFuncSetAttribute(gemm_f16<2>, cudaFuncAttributeMaxDynamicSharedMemorySize, GEMM_SMEM);
        attr_done = true;
    }

    prep_kernel<<<(NN * 128 + 1023) / 1024, 1024>>>(agg, cnt, sum, sumsq, wt,
                                                    w1a, w1b, w2a, w2b);

    // edge layer 1: h1 = concat(message, x[row]) @ w1a   (+stats slot 0)
    gemm_f16<0><<<EE / 128, 256, GEMM_SMEM>>>(message, x, nullptr, row, nullptr,
                                 nullptr, nullptr, nullptr, nullptr, 0.f,
                                 wt, h1, EE, sum + 0, sumsq + 0);

    // edge layer 2: h2 = relu(bn1a(h1)) @ w1b            (+stats slot 1)
    gemm_f16<1><<<EE / 128, 256, GEMM_SMEM>>>(nullptr, nullptr, h1, nullptr, nullptr,
                                 sum + 0, sumsq + 0, g1a, be1a, 1.0f / EE,
                                 wt + 32768, h2, EE, sum + 128, sumsq + 128);

    // scatter-mean numerator + counts (bn1b+relu fused, div fused into next gemm)
    scatter_kernel<<<EE / 8, 256>>>(h2, col, sum + 128, sumsq + 128, g1b, be1b,
                                    agg, cnt);

    // node layer 1: o1 = concat(x, agg/cnt) @ w2a        (+stats slot 2)
    gemm_f16<2><<<(NN + 127) / 128, 256, GEMM_SMEM>>>(x, agg, nullptr, nullptr, cnt,
                                 nullptr, nullptr, nullptr, nullptr, 0.f,
                                 wt + 49152, o1, NN, sum + 256, sumsq + 256);

    // node layer 2: o2 = relu(bn2a(o1)) @ w2b            (+stats slot 3)
    gemm_f16<1><<<(NN + 127) / 128, 256, GEMM_SMEM>>>(nullptr, nullptr, o1, nullptr, nullptr,
                                 sum + 256, sumsq + 256, g2a, be2a, 1.0f / NN,
                                 wt + 81920, o2, NN, sum + 384, sumsq + 384);

    // output: o (N*128 floats) then attn (N floats)
    output_kernel<<<NN, 128>>>(o2, sum + 384, sumsq + 384, g2b, be2b, wa, ba, out);
}

// round 6
// speedup vs baseline: 2.1029x; 1.0407x over previous
#include <cuda_runtime.h>
#include <cuda_fp16.h>
#include <cstdint>
#include <cmath>

// Problem constants (fixed by the dataset)
#define EE 800000
#define NN 50000
#define BN_EPS 1e-5f

// ---------------------------------------------------------------------------
// Scratch (device globals; no runtime allocation)
// ---------------------------------------------------------------------------
__device__ __align__(16) __half g_h1[(size_t)EE * 128];
__device__ __align__(16) __half g_h2[(size_t)EE * 128];
__device__ __align__(16) __half g_o1[(size_t)NN * 128];
__device__ __align__(16) __half g_o2[(size_t)NN * 128];
__device__ __align__(16) float  g_xw[(size_t)NN * 128];   // x @ w1a[128:256]
__device__ float g_agg[(size_t)NN * 128];
__device__ int   g_cnt[NN];
__device__ float g_sum  [512];                  // 4 layers x 128 col sums
__device__ float g_sumsq[512];                  // 4 layers x 128 col sumsq
__device__ __align__(16) __half g_wt16[98304];  // transposed fp16 weights

// weight slice offsets inside g_wt16 (all [n][k] K-major rows)
#define WT_LO  0        // w1a rows   0..127  (K=128)
#define WT_HI  16384    // w1a rows 128..255  (K=128)
#define WT_W1B 32768    // w1b                (K=128)
#define WT_W2A 49152    // w2a                (K=256)
#define WT_W2B 81920    // w2b                (K=128)

// ---------------------------------------------------------------------------
// Helpers
// ---------------------------------------------------------------------------
__device__ __forceinline__ uint32_t packh2(float a, float b) {
    __half2 h = __floats2half2_rn(a, b);
    return *(uint32_t*)&h;
}

__device__ __forceinline__ uint32_t smem_u32(const void* p) {
    return (uint32_t)__cvta_generic_to_shared(p);
}

__device__ __forceinline__ void cp_async16(uint32_t dst, const void* src) {
    asm volatile("cp.async.cg.shared.global [%0], [%1], 16;"
                 :: "r"(dst), "l"(src));
}
__device__ __forceinline__ void cp_commit() {
    asm volatile("cp.async.commit_group;" ::: "memory");
}
__device__ __forceinline__ void cp_wait0() {
    asm volatile("cp.async.wait_group 0;" ::: "memory");
}

__device__ __forceinline__ void red_add_v4(float* p, float4 v) {
    asm volatile("red.global.add.v4.f32 [%0], {%1,%2,%3,%4};"
                 :: "l"(p), "f"(v.x), "f"(v.y), "f"(v.z), "f"(v.w) : "memory");
}

// ldmatrix: four 8x8 b16 matrices (non-transposed)
__device__ __forceinline__ void ldsm_x4(uint32_t& r0, uint32_t& r1,
                                        uint32_t& r2, uint32_t& r3,
                                        uint32_t addr) {
    asm volatile("ldmatrix.sync.aligned.m8n8.x4.shared.b16 {%0,%1,%2,%3}, [%4];"
                 : "=r"(r0), "=r"(r1), "=r"(r2), "=r"(r3) : "r"(addr));
}

// mma.m16n8k16 fp16 in, fp32 accumulate
__device__ __forceinline__ void mma_f16(float* c, const uint32_t* a,
                                        uint32_t b0, uint32_t b1) {
    asm volatile(
        "mma.sync.aligned.m16n8k16.row.col.f32.f16.f16.f32 "
        "{%0,%1,%2,%3}, {%4,%5,%6,%7}, {%8,%9}, {%0,%1,%2,%3};"
        : "+f"(c[0]), "+f"(c[1]), "+f"(c[2]), "+f"(c[3])
        : "r"(a[0]), "r"(a[1]), "r"(a[2]), "r"(a[3]), "r"(b0), "r"(b1));
}

__device__ __forceinline__ void sts_v4(uint32_t dst, uint4 o) {
    asm volatile("st.shared.v4.b32 [%0], {%1,%2,%3,%4};"
                 :: "r"(dst), "r"(o.x), "r"(o.y), "r"(o.z), "r"(o.w));
}

// ---------------------------------------------------------------------------
// prep: zero accumulators + transpose/convert weights to [n][k] fp16 slices
// ---------------------------------------------------------------------------
__global__ void prep_kernel(float* __restrict__ agg, int* __restrict__ cnt,
                            float* __restrict__ sum, float* __restrict__ sumsq,
                            __half* __restrict__ wt,
                            const float* __restrict__ w1a, const float* __restrict__ w1b,
                            const float* __restrict__ w2a, const float* __restrict__ w2b)
{
    int idx = blockIdx.x * blockDim.x + threadIdx.x;
    if (idx < NN * 128) agg[idx] = 0.f;
    if (idx < NN)       cnt[idx] = 0;
    if (idx < 512) { sum[idx] = 0.f; sumsq[idx] = 0.f; }
    if (idx < 98304) {
        float v;
        if (idx < 16384) {                        // w1a lo: k 0..127
            int n = idx >> 7, k = idx & 127;
            v = w1a[k * 128 + n];
        } else if (idx < 32768) {                 // w1a hi: k 128..255
            int i = idx - 16384, n = i >> 7, k = i & 127;
            v = w1a[(128 + k) * 128 + n];
        } else if (idx < 49152) {                 // w1b
            int i = idx - 32768, n = i >> 7, k = i & 127;
            v = w1b[k * 128 + n];
        } else if (idx < 81920) {                 // w2a: K=256
            int i = idx - 49152, n = i >> 8, k = i & 255;
            v = w2a[k * 128 + n];
        } else {                                  // w2b
            int i = idx - 81920, n = i >> 7, k = i & 127;
            v = w2b[k * 128 + n];
        }
        wt[idx] = __float2half_rn(v);
    }
}

// ---------------------------------------------------------------------------
// fp16 tensor-core GEMM: out[M,128] = A[M,K] @ W[K,128], fused BN-stat epilogue.
// MODE 0: A = message (K=128); epilogue acc += xw[row[r]] BEFORE stats
// MODE 1: A = relu(prev*scale + shift)     (K=128, f16 source)
// MODE 2: A = concat(x, agg_sum*inv_cnt)   (K=256, f32 sources)
// MODE 3: A = x (K=128, f32); plain gemm, f32 out, no stats (xw precompute)
// Register-software-pipelined A path (LDG before MMA block, STS after); B via
// cp.async. Invalid rows forced to exact zeros (exact fused stats).
// ---------------------------------------------------------------------------
template<int MODE>
__launch_bounds__(256, 2)
__global__ void gemm_f16(
    const float*  __restrict__ A0f,   // mode0: message; mode2/3: x
    const float*  __restrict__ A1f,   // mode2: agg sums
    const __half* __restrict__ A0h,   // mode1: prev activations (f16)
    const float*  __restrict__ xw,    // mode0: per-node x@w1a_hi (f32)
    const int*    __restrict__ ridx,  // mode0: edge row indices
    const int*    __restrict__ cnt,   // mode2: per-node counts
    const float*  __restrict__ psum,  // mode1: prev-layer col sums
    const float*  __restrict__ psq,   // mode1: prev-layer col sumsq
    const float*  __restrict__ gamma, // mode1
    const float*  __restrict__ beta,  // mode1
    float         invPrevM,           // mode1
    const __half* __restrict__ Wt,    // [128][K] fp16, K-major rows
    __half* __restrict__ Hout,        // [M,128] fp16 (modes 0,1,2)
    float*  __restrict__ Hout32,      // [M,128] f32  (mode 3)
    int M,
    float* __restrict__ osum,         // this layer's col-sum slot
    float* __restrict__ osq)          // this layer's col-sumsq slot
{
    constexpr int K   = (MODE == 2) ? 256 : 128;
    constexpr int NIT = K / 64;

    extern __shared__ char dyns[];
    const uint32_t raw   = smem_u32(dyns);
    const uint32_t sbase = (raw + 1023u) & ~1023u;
    char* gbase = dyns + (sbase - raw);
    // layout (fp16 tiles, 128 rows x 64 k = 16KB each):
    // A buf0 @0, A buf1 @16384, B buf0 @32768, B buf1 @49152
    // epilogue staging reuses this region (f16: 32KB, f32: 64KB).

    __shared__ int   sRow[128];
    __shared__ float sInv[128], sScl[128], sSft[128];
    __shared__ float sSum[128], sSq[128];

    const int tid  = threadIdx.x;
    const int warp = tid >> 5;
    const int lane = tid & 31;
    const int bm   = blockIdx.x * 128;

    if (tid < 128) { sSum[tid] = 0.f; sSq[tid] = 0.f; }
    if (MODE == 0 && tid < 128) sRow[tid] = ridx[bm + tid];
    if (MODE == 2 && tid < 128) {
        int r = bm + tid;
        int c = (r < M) ? cnt[r] : 1;
        sInv[tid] = 1.0f / (float)(c > 1 ? c : 1);
    }
    if (MODE == 1 && tid < 128) {
        float m  = psum[tid] * invPrevM;
        float v  = fmaxf(psq[tid] * invPrevM - m * m, 0.f);
        float sc = gamma[tid] * rsqrtf(v + BN_EPS);
        sScl[tid] = sc;
        sSft[tid] = beta[tid] - m * sc;
    }
    __syncthreads();

    // ---- raw A loads for chunk it (no transform; pure LDG issue) ----
    auto ldgA = [&](int it, float4* pf, uint4* ph) {
        const int k0 = it * 64;
#pragma unroll
        for (int j = 0; j < 4; j++) {
            int u = tid + j * 256, row = u >> 3, unit = u & 7;
            int kg = k0 + unit * 8;
            int rg = bm + row;
            if (MODE == 1) {
                ph[j] = (rg < M) ? *(const uint4*)(A0h + (size_t)rg * 128 + kg)
                                 : make_uint4(0, 0, 0, 0);
            } else if (MODE == 0) {
                const float* src = A0f + (size_t)rg * 128 + kg;  // EE % 128 == 0
                pf[2 * j]     = *(const float4*)src;
                pf[2 * j + 1] = *(const float4*)(src + 4);
            } else { // MODE 2 / 3
                if (rg < M) {
                    const float* src = (MODE == 3 || kg < 128)
                        ? (A0f + (size_t)rg * 128 + (MODE == 3 ? kg : kg))
                        : (A1f + (size_t)rg * 128 + (kg - 128));
                    pf[2 * j]     = *(const float4*)src;
                    pf[2 * j + 1] = *(const float4*)(src + 4);
                } else {
                    pf[2 * j]     = make_float4(0, 0, 0, 0);
                    pf[2 * j + 1] = make_float4(0, 0, 0, 0);
                }
            }
        }
    };

    // ---- transform + pack + STS for chunk it into buffer s ----
    auto stsA = [&](int it, int s, const float4* pf, const uint4* ph) {
        const int k0 = it * 64;
        const uint32_t aB = sbase + (uint32_t)s * 16384u;
#pragma unroll
        for (int j = 0; j < 4; j++) {
            int u = tid + j * 256, row = u >> 3, unit = u & 7;
            int kg = k0 + unit * 8;
            int rg = bm + row;
            uint32_t dst = aB + (uint32_t)(row * 128 + ((unit ^ (row & 7)) << 4));
            uint4 o;
            if (MODE == 0) {
                float4 p = pf[2 * j], q = pf[2 * j + 1];
                o.x = packh2(p.x, p.y); o.y = packh2(p.z, p.w);
                o.z = packh2(q.x, q.y); o.w = packh2(q.z, q.w);
            } else if (MODE == 1) {
                if (rg < M) {
                    uint4 rv = ph[j];
                    float4 sc0 = *(const float4*)(sScl + kg);
                    float4 sc1 = *(const float4*)(sScl + kg + 4);
                    float4 sf0 = *(const float4*)(sSft + kg);
                    float4 sf1 = *(const float4*)(sSft + kg + 4);
                    float2 v0 = __half22float2(*(__half2*)&rv.x);
                    float2 v1 = __half22float2(*(__half2*)&rv.y);
                    float2 v2 = __half22float2(*(__half2*)&rv.z);
                    float2 v3 = __half22float2(*(__half2*)&rv.w);
                    o.x = packh2(fmaxf(fmaf(v0.x, sc0.x, sf0.x), 0.f),
                                 fmaxf(fmaf(v0.y, sc0.y, sf0.y), 0.f));
                    o.y = packh2(fmaxf(fmaf(v1.x, sc0.z, sf0.z), 0.f),
                                 fmaxf(fmaf(v1.y, sc0.w, sf0.w), 0.f));
                    o.z = packh2(fmaxf(fmaf(v2.x, sc1.x, sf1.x), 0.f),
                                 fmaxf(fmaf(v2.y, sc1.y, sf1.y), 0.f));
                    o.w = packh2(fmaxf(fmaf(v3.x, sc1.z, sf1.z), 0.f),
                                 fmaxf(fmaf(v3.y, sc1.w, sf1.w), 0.f));
                } else {
                    o = make_uint4(0, 0, 0, 0);
                }
            } else { // MODE 2 / 3
                if (rg < M) {
                    float4 p = pf[2 * j], q = pf[2 * j + 1];
                    if (MODE == 2 && kg >= 128) {
                        float iv = sInv[row];
                        p.x *= iv; p.y *= iv; p.z *= iv; p.w *= iv;
                        q.x *= iv; q.y *= iv; q.z *= iv; q.w *= iv;
                    }
                    o.x = packh2(p.x, p.y); o.y = packh2(p.z, p.w);
                    o.z = packh2(q.x, q.y); o.w = packh2(q.z, q.w);
                } else {
                    o = make_uint4(0, 0, 0, 0);
                }
            }
            sts_v4(dst, o);
        }
    };

    // ---- B staging via cp.async (pre-converted fp16 weights) ----
    auto cpB = [&](int it, int s) {
        const int k0 = it * 64;
        const uint32_t bB = sbase + 32768u + (uint32_t)s * 16384u;
#pragma unroll
        for (int j = 0; j < 4; j++) {
            int u = tid + j * 256, n = u >> 3, unit = u & 7;
            uint32_t dst = bB + (uint32_t)(n * 128 + ((unit ^ (n & 7)) << 4));
            cp_async16(dst, Wt + (size_t)n * K + k0 + unit * 8);
        }
        cp_commit();
    };

    float acc[2][8][4];
#pragma unroll
    for (int mi = 0; mi < 2; mi++)
#pragma unroll
        for (int ni = 0; ni < 8; ni++)
#pragma unroll
            for (int v = 0; v < 4; v++) acc[mi][ni][v] = 0.0f;

    const int g   = lane >> 2;
    const int t4  = lane & 3;
    const int wm  = warp & 3;
    const int wn  = warp >> 2;
    const int wr  = wm * 32;
    const int wcc = wn * 64;

    // ldmatrix per-lane row indices (fixed across chunk/step)
    int rA[2], rB[4];
#pragma unroll
    for (int mi = 0; mi < 2; mi++)
        rA[mi] = wr + mi * 16 + (lane & 7) + ((lane >> 3) & 1) * 8;
#pragma unroll
    for (int p = 0; p < 4; p++)
        rB[p] = wcc + p * 16 + (lane & 7) + ((lane >> 3) & 1) * 8;
    const int uHi = (lane >> 4);   // +8 k-offset selector within ldmatrix.x4

    // ---- prologue: chunk 0 staged synchronously ----
    {
        float4 pf[8]; uint4 ph[4];
        ldgA(0, pf, ph);
        stsA(0, 0, pf, ph);
        cpB(0, 0);
    }

#pragma unroll 1
    for (int it = 0; it < NIT; it++) {
        const int s = it & 1;
        cp_wait0();            // B(it) arrived (only group in flight)
        __syncthreads();       // A(it) STS visible; all warps done chunk it-1

        float4 pf[8]; uint4 ph[4];
        const bool more = (it + 1 < NIT);
        if (more) {
            ldgA(it + 1, pf, ph);   // raw loads issued BEFORE compute
            cpB(it + 1, s ^ 1);
        }

        const uint32_t aB = sbase + (uint32_t)s * 16384u;
        const uint32_t bB = sbase + 32768u + (uint32_t)s * 16384u;

#pragma unroll
        for (int step = 0; step < 4; step++) {
            const int unit = step * 2 + uHi;
            uint32_t a[2][4];
#pragma unroll
            for (int mi = 0; mi < 2; mi++)
                ldsm_x4(a[mi][0], a[mi][1], a[mi][2], a[mi][3],
                        aB + (uint32_t)(rA[mi] * 128 + ((unit ^ (rA[mi] & 7)) << 4)));
#pragma unroll
            for (int p = 0; p < 4; p++) {
                uint32_t b0, b1, b2, b3;
                ldsm_x4(b0, b1, b2, b3,
                        bB + (uint32_t)(rB[p] * 128 + ((unit ^ (rB[p] & 7)) << 4)));
#pragma unroll
                for (int mi = 0; mi < 2; mi++) {
                    mma_f16(acc[mi][2 * p],     a[mi], b0, b2);
                    mma_f16(acc[mi][2 * p + 1], a[mi], b1, b3);
                }
            }
        }

        if (more) stsA(it + 1, s ^ 1, pf, ph);  // consume raw loads after MMA
    }

    // ---- MODE 0: add per-node xw contribution BEFORE stats ----
    if (MODE == 0) {
#pragma unroll
        for (int mi = 0; mi < 2; mi++) {
            const float* x0 = xw + (size_t)sRow[wr + mi * 16 + g]     * 128;
            const float* x1 = xw + (size_t)sRow[wr + mi * 16 + g + 8] * 128;
#pragma unroll
            for (int ni = 0; ni < 8; ni++) {
                int col = wcc + ni * 8 + 2 * t4;
                float2 u0 = *(const float2*)(x0 + col);
                float2 u1 = *(const float2*)(x1 + col);
                acc[mi][ni][0] += u0.x; acc[mi][ni][1] += u0.y;
                acc[mi][ni][2] += u1.x; acc[mi][ni][3] += u1.y;
            }
        }
    }

    // ---- fused BN-stat reduction (padded rows are exact zeros) ----
    if (MODE != 3) {
#pragma unroll
        for (int ni = 0; ni < 8; ni++) {
            float s0 = 0, q0 = 0, s1 = 0, q1 = 0;
#pragma unroll
            for (int mi = 0; mi < 2; mi++) {
                float a0 = acc[mi][ni][0], a2 = acc[mi][ni][2];
                float a1 = acc[mi][ni][1], a3 = acc[mi][ni][3];
                s0 += a0 + a2; q0 += a0 * a0 + a2 * a2;
                s1 += a1 + a3; q1 += a1 * a1 + a3 * a3;
            }
#pragma unroll
            for (int off = 4; off < 32; off <<= 1) {
                s0 += __shfl_xor_sync(0xFFFFFFFFu, s0, off);
                q0 += __shfl_xor_sync(0xFFFFFFFFu, q0, off);
                s1 += __shfl_xor_sync(0xFFFFFFFFu, s1, off);
                q1 += __shfl_xor_sync(0xFFFFFFFFu, q1, off);
            }
            if (lane < 4) {
                int c0 = wcc + ni * 8 + 2 * t4;
                atomicAdd(&sSum[c0],     s0); atomicAdd(&sSq[c0],     q0);
                atomicAdd(&sSum[c0 + 1], s1); atomicAdd(&sSq[c0 + 1], q1);
            }
        }
    }

    __syncthreads();                     // all ldmatrix reads of A/B done
    char* epi = gbase;

    if (MODE == 3) {
        // ---- f32 epilogue: acc -> smem (512B rows, swizzled) -> STG ----
#pragma unroll
        for (int mi = 0; mi < 2; mi++) {
            int r0 = wr + mi * 16 + g;
            int r1 = r0 + 8;
#pragma unroll
            for (int ni = 0; ni < 8; ni++) {
                int col = wcc + ni * 8 + 2 * t4;
                *(float2*)(epi + r0 * 512 + ((col * 4) ^ ((r0 & 7) << 5))) =
                    make_float2(acc[mi][ni][0], acc[mi][ni][1]);
                *(float2*)(epi + r1 * 512 + ((col * 4) ^ ((r1 & 7) << 5))) =
                    make_float2(acc[mi][ni][2], acc[mi][ni][3]);
            }
        }
        __syncthreads();
#pragma unroll
        for (int i = 0; i < 16; i++) {
            int gid = tid + i * 256;
            int row = gid >> 5;
            int seg = gid & 31;
            if (bm + row < M) {
                uint4 v = *(uint4*)(epi + row * 512 + ((seg * 16) ^ ((row & 7) << 5)));
                *(uint4*)(Hout32 + (size_t)(bm + row) * 128 + seg * 4) = v;
            }
        }
        return;
    }

    // ---- f16 epilogue: acc -> smem (256B rows, swizzled) -> STG ----
#pragma unroll
    for (int mi = 0; mi < 2; mi++) {
        int r0 = wr + mi * 16 + g;
        int r1 = r0 + 8;
#pragma unroll
        for (int ni = 0; ni < 8; ni++) {
            int col = wcc + ni * 8 + 2 * t4;
            *(uint32_t*)(epi + r0 * 256 + ((col * 2) ^ ((r0 & 7) << 5))) =
                packh2(acc[mi][ni][0], acc[mi][ni][1]);
            *(uint32_t*)(epi + r1 * 256 + ((col * 2) ^ ((r1 & 7) << 5))) =
                packh2(acc[mi][ni][2], acc[mi][ni][3]);
        }
    }
    __syncthreads();
#pragma unroll
    for (int i = 0; i < 8; i++) {
        int gid = tid + i * 256;
        int row = gid >> 4;
        int seg = gid & 15;
        if (bm + row < M) {
            uint4 v = *(uint4*)(epi + row * 256 + ((seg * 16) ^ ((row & 7) << 5)));
            *(uint4*)(Hout + (size_t)(bm + row) * 128 + seg * 8) = v;
        }
    }

    if (tid < 128) {
        atomicAdd(osum + tid, sSum[tid]);
        atomicAdd(osq  + tid, sSq[tid]);
    }
}

// ---------------------------------------------------------------------------
// Scatter: agg[col[e]] += relu(bn(h2_f16[e])), cnt[col[e]] += 1 (warp/edge)
// ---------------------------------------------------------------------------
__global__ void scatter_kernel(const __half* __restrict__ h2,
                               const int* __restrict__ col,
                               const float* __restrict__ psum,
                               const float* __restrict__ psq,
                               const float* __restrict__ gamma,
                               const float* __restrict__ beta,
                               float* __restrict__ agg, int* __restrict__ cnt)
{
    __shared__ float sScl[128], sSft[128];
    int t = threadIdx.x;                 // 256
    if (t < 128) {
        float m  = psum[t] * (1.0f / EE);
        float v  = fmaxf(psq[t] * (1.0f / EE) - m * m, 0.f);
        float sc = gamma[t] * rsqrtf(v + BN_EPS);
        sScl[t] = sc;
        sSft[t] = beta[t] - m * sc;
    }
    __syncthreads();

    int e    = blockIdx.x * 8 + (t >> 5);
    int lane = t & 31;
    int c    = __ldg(col + e);
    uint2 rawv = *(const uint2*)(h2 + (size_t)e * 128 + lane * 4);
    float2 a = __half22float2(*(__half2*)&rawv.x);
    float2 b = __half22float2(*(__half2*)&rawv.y);
    float4 sc = *(const float4*)(sScl + lane * 4);
    float4 sf = *(const float4*)(sSft + lane * 4);
    float4 v;
    v.x = fmaxf(fmaf(a.x, sc.x, sf.x), 0.f);
    v.y = fmaxf(fmaf(a.y, sc.y, sf.y), 0.f);
    v.z = fmaxf(fmaf(b.x, sc.z, sf.z), 0.f);
    v.w = fmaxf(fmaf(b.y, sc.w, sf.w), 0.f);
    red_add_v4(agg + (size_t)c * 128 + lane * 4, v);
    if (lane == 0) atomicAdd(cnt + c, 1);
}

// ---------------------------------------------------------------------------
// Final: o = relu(bn(o2)); attn = sigmoid(o @ wa + ba)
// ---------------------------------------------------------------------------
__global__ void output_kernel(const __half* __restrict__ o2,
                              const float* __restrict__ psum,
                              const float* __restrict__ psq,
                              const float* __restrict__ gamma,
                              const float* __restrict__ beta,
                              const float* __restrict__ wa,
                              const float* __restrict__ ba,
                              float* __restrict__ out)
{
    __shared__ float red[4];
    int n = blockIdx.x;
    int t = threadIdx.x;                 // 128
    float m  = psum[t] * (1.0f / NN);
    float vv = fmaxf(psq[t] * (1.0f / NN) - m * m, 0.f);
    float sc = gamma[t] * rsqrtf(vv + BN_EPS);
    float sf = beta[t] - m * sc;

    float v = __half2float(o2[(size_t)n * 128 + t]);
    v = fmaxf(fmaf(v, sc, sf), 0.f);
    out[(size_t)n * 128 + t] = v;

    float p = v * wa[t];
#pragma unroll
    for (int off = 16; off > 0; off >>= 1)
        p += __shfl_xor_sync(0xFFFFFFFFu, p, off);
    if ((t & 31) == 0) red[t >> 5] = p;
    __syncthreads();
    if (t == 0) {
        float d = red[0] + red[1] + red[2] + red[3] + ba[0];
        out[(size_t)NN * 128 + n] = 1.0f / (1.0f + expf(-d));
    }
}

// ---------------------------------------------------------------------------
// Launch
// ---------------------------------------------------------------------------
#define GEMM_SMEM (65536 + 1024)

extern "C" void kernel_launch(void* const* d_in, const int* in_sizes, int n_in,
                              void* d_out, int out_size)
{
    const float* x       = (const float*)d_in[0];
    const int*   ei      = (const int*)  d_in[1];   // [2,E]: row then col
    const float* message = (const float*)d_in[2];
    const float* w1a  = (const float*)d_in[3];
    const float* g1a  = (const float*)d_in[5];
    const float* be1a = (const float*)d_in[6];
    const float* w1b  = (const float*)d_in[7];
    const float* g1b  = (const float*)d_in[9];
    const float* be1b = (const float*)d_in[10];
    const float* w2a  = (const float*)d_in[11];
    const float* g2a  = (const float*)d_in[13];
    const float* be2a = (const float*)d_in[14];
    const float* w2b  = (const float*)d_in[15];
    const float* g2b  = (const float*)d_in[17];
    const float* be2b = (const float*)d_in[18];
    const float* wa   = (const float*)d_in[19];
    const float* ba   = (const float*)d_in[20];
    float* out = (float*)d_out;

    __half *h1, *h2, *o1, *o2, *wt;
    float *agg, *sum, *sumsq, *xw;
    int* cnt;
    cudaGetSymbolAddress((void**)&h1,    g_h1);
    cudaGetSymbolAddress((void**)&h2,    g_h2);
    cudaGetSymbolAddress((void**)&o1,    g_o1);
    cudaGetSymbolAddress((void**)&o2,    g_o2);
    cudaGetSymbolAddress((void**)&xw,    g_xw);
    cudaGetSymbolAddress((void**)&agg,   g_agg);
    cudaGetSymbolAddress((void**)&cnt,   g_cnt);
    cudaGetSymbolAddress((void**)&sum,   g_sum);
    cudaGetSymbolAddress((void**)&sumsq, g_sumsq);
    cudaGetSymbolAddress((void**)&wt,    g_wt16);

    const int* row = ei;
    const int* col = ei + EE;

    static bool attr_done = false;
    if (!attr_done) {
        cudaFuncSetAttribute(gemm_f16<0>, cudaFuncAttributeMaxDynamicSharedMemorySize, GEMM_SMEM);
        cudaFuncSetAttribute(gemm_f16<1>, cudaFuncAttributeMaxDynamicSharedMemorySize, GEMM_SMEM);
        cudaFuncSetAttribute(gemm_f16<2>, cudaFuncAttributeMaxDynamicSharedMemorySize, GEMM_SMEM);
        cudaFuncSetAttribute(gemm_f16<3>, cudaFuncAttributeMaxDynamicSharedMemorySize, GEMM_SMEM);
        attr_done = true;
    }

    prep_kernel<<<(NN * 128 + 1023) / 1024, 1024>>>(agg, cnt, sum, sumsq, wt,
                                                    w1a, w1b, w2a, w2b);

    // xw = x @ w1a[128:256]  (f32 out, no stats)
    gemm_f16<3><<<(NN + 127) / 128, 256, GEMM_SMEM>>>(x, nullptr, nullptr, nullptr,
                                 nullptr, nullptr, nullptr, nullptr, nullptr, nullptr, 0.f,
                                 wt + WT_HI, nullptr, xw, NN, nullptr, nullptr);

    // edge layer 1: h1 = message @ w1a_lo + xw[row]      (+stats slot 0)
    gemm_f16<0><<<EE / 128, 256, GEMM_SMEM>>>(message, nullptr, nullptr, xw, row,
                                 nullptr, nullptr, nullptr, nullptr, nullptr, 0.f,
                                 wt + WT_LO, h1, nullptr, EE, sum + 0, sumsq + 0);

    // edge layer 2: h2 = relu(bn1a(h1)) @ w1b            (+stats slot 1)
    gemm_f16<1><<<EE / 128, 256, GEMM_SMEM>>>(nullptr, nullptr, h1, nullptr, nullptr,
                                 nullptr, sum + 0, sumsq + 0, g1a, be1a, 1.0f / EE,
                                 wt + WT_W1B, h2, nullptr, EE, sum + 128, sumsq + 128);

    // scatter-mean numerator + counts (bn1b+relu fused, div fused into next gemm)
    scatter_kernel<<<EE / 8, 256>>>(h2, col, sum + 128, sumsq + 128, g1b, be1b,
                                    agg, cnt);

    // node layer 1: o1 = concat(x, agg/cnt) @ w2a        (+stats slot 2)
    gemm_f16<2><<<(NN + 127) / 128, 256, GEMM_SMEM>>>(x, agg, nullptr, nullptr,
                                 nullptr, cnt, nullptr, nullptr, nullptr, nullptr, 0.f,
                                 wt + WT_W2A, o1, nullptr, NN, sum + 256, sumsq + 256);

    // node layer 2: o2 = relu(bn2a(o1)) @ w2b            (+stats slot 3)
    gemm_f16<1><<<(NN + 127) / 128, 256, GEMM_SMEM>>>(nullptr, nullptr, o1, nullptr, nullptr,
                                 nullptr, sum + 256, sumsq + 256, g2a, be2a, 1.0f / NN,
                                 wt + WT_W2B, o2, nullptr, NN, sum + 384, sumsq + 384);

    // output: o (N*128 floats) then attn (N floats)
    output_kernel<<<NN, 128>>>(o2, sum + 384, sumsq + 384, g2b, be2b, wa, ba, out);
}